// round 4
// baseline (speedup 1.0000x reference)
#include <cuda_runtime.h>
#include <math.h>

#define HD    512
#define GATES 2048
#define NB    1024
#define SEQ   256
#define CH    128
#define NCLS  40
#define NBLK  128          // 16 j-tiles x 8 m-tiles, <= 148 SMs (co-resident)
#define NTHR  256

// ---------------- persistent device scratch (allocation-free) ----------------
__device__ float g_h0[2][NB * HD];
__device__ float g_c0[NB * HD];
__device__ float g_h1[2][NB * HD];
__device__ float g_c1[NB * HD];
__device__ float g_cls_sum;
__device__ float g_bbox_sum;
__device__ int   g_correct;
__device__ unsigned g_bar_count;   // always returns to 0 after each barrier
__device__ unsigned g_bar_phase;   // monotonic across launches

// ---------------- software grid barrier --------------------------------------
// Every block reads g_bar_phase BEFORE its first arrive; the barrier cannot
// complete until all blocks arrive, so all initial reads happen-before any
// phase bump. Monotonic phase => replay-safe with no reset needed.
__device__ __forceinline__ void grid_bar(unsigned& my_phase) {
    __syncthreads();
    if (threadIdx.x == 0) {
        __threadfence();
        unsigned old = atomicAdd(&g_bar_count, 1u);
        if (old == NBLK - 1) {
            g_bar_count = 0;
            __threadfence();
            atomicExch(&g_bar_phase, my_phase + 1u);
        } else {
            while (atomicAdd(&g_bar_phase, 0u) <= my_phase) __nanosleep(64);
        }
        __threadfence();
    }
    my_phase++;
    __syncthreads();
}

// ---------------- one LSTM layer-step tile (GEMM + fused cell update) --------
// Block (mt, jt) computes gates for rows [mt*128, +128) and hidden units
// jj in [jt*32, +32), all 4 gates. Tile column c (0..127):
//   gate = c & 3,  jj = j0 + (c >> 2)   (gate row in W = gate*HD + jj)
__device__ __forceinline__ void lstm_tile(
    const float* __restrict__ Ax, int axs, int Kx,   // x input, row stride, K
    const float* __restrict__ Wih,                   // [GATES, Kx]
    const float* __restrict__ Ah,                    // h_prev, stride HD
    const float* __restrict__ Whh,                   // [GATES, HD]
    const float* __restrict__ bias,                  // [GATES]
    float* __restrict__ cbuf,                        // [NB*HD] (exclusive per elem)
    float* __restrict__ hout,                        // h_new  (double buffer)
    float (*As)[128], float (*Bs)[128])
{
    const int tid  = threadIdx.x;
    const int tx   = tid & 15;
    const int ty   = tid >> 4;
    const int mt   = blockIdx.x >> 4;
    const int jt   = blockIdx.x & 15;
    const int row0 = mt * 128;
    const int j0   = jt * 32;

    float acc[8][8];
    #pragma unroll
    for (int i = 0; i < 8; ++i)
        #pragma unroll
        for (int j = 0; j < 8; ++j) acc[i][j] = 0.f;

    #pragma unroll 1
    for (int phase = 0; phase < 2; ++phase) {
        const float* A    = phase ? Ah  : Ax;
        const int    as   = phase ? HD  : axs;
        const float* B    = phase ? Whh : Wih;
        const int    bstr = phase ? HD  : Kx;
        const int    K    = phase ? HD  : Kx;

        for (int k0 = 0; k0 < K; k0 += 16) {
            #pragma unroll
            for (int l = 0; l < 2; ++l) {
                int idx = tid + l * 256;
                int r   = idx >> 2;
                int kq  = (idx & 3) * 4;
                float4 va = *reinterpret_cast<const float4*>(
                    &A[(size_t)(row0 + r) * as + k0 + kq]);
                As[kq + 0][r] = va.x; As[kq + 1][r] = va.y;
                As[kq + 2][r] = va.z; As[kq + 3][r] = va.w;
                int grow = (r & 3) * HD + j0 + (r >> 2);   // permuted gate row
                float4 vb = *reinterpret_cast<const float4*>(
                    &B[(size_t)grow * bstr + k0 + kq]);
                Bs[kq + 0][r] = vb.x; Bs[kq + 1][r] = vb.y;
                Bs[kq + 2][r] = vb.z; Bs[kq + 3][r] = vb.w;
            }
            __syncthreads();

            #pragma unroll
            for (int k = 0; k < 16; ++k) {
                float a[8], b[8];
                #pragma unroll
                for (int i = 0; i < 8; ++i) a[i] = As[k][ty * 8 + i];
                #pragma unroll
                for (int j = 0; j < 8; ++j) b[j] = Bs[k][tx * 8 + j];
                #pragma unroll
                for (int i = 0; i < 8; ++i)
                    #pragma unroll
                    for (int j = 0; j < 8; ++j)
                        acc[i][j] += a[i] * b[j];
            }
            __syncthreads();
        }
    }

    // fused epilogue: bias + LSTM cell pointwise, write c and h_new
    #pragma unroll
    for (int i = 0; i < 8; ++i) {
        int m = row0 + ty * 8 + i;
        #pragma unroll
        for (int g2 = 0; g2 < 2; ++g2) {
            int jj = j0 + tx * 2 + g2;
            float gi = acc[i][g2 * 4 + 0] + bias[0 * HD + jj];
            float gf = acc[i][g2 * 4 + 1] + bias[1 * HD + jj];
            float gg = acc[i][g2 * 4 + 2] + bias[2 * HD + jj];
            float go = acc[i][g2 * 4 + 3] + bias[3 * HD + jj];
            float si = 1.f / (1.f + expf(-gi));
            float sf = 1.f / (1.f + expf(-gf));
            float so = 1.f / (1.f + expf(-go));
            size_t idx = (size_t)m * HD + jj;
            float cv = sf * cbuf[idx] + si * tanhf(gg);
            cbuf[idx] = cv;
            hout[idx] = so * tanhf(cv);
        }
    }
}

// ---------------- the whole network in one persistent kernel -----------------
__global__ __launch_bounds__(NTHR)
void rlstm_persistent(const float* __restrict__ data,
                      const int*   __restrict__ labels,
                      const float* __restrict__ props,
                      const float* __restrict__ Wih0, const float* __restrict__ Whh0,
                      const float* __restrict__ b0,
                      const float* __restrict__ Wih1, const float* __restrict__ Whh1,
                      const float* __restrict__ b1,
                      const float* __restrict__ Wcls, const float* __restrict__ bcls,
                      const float* __restrict__ Wbbox, const float* __restrict__ bbbox,
                      float* __restrict__ out)
{
    __shared__ float As[16][128];
    __shared__ float Bs[16][128];

    const int tid = threadIdx.x;
    unsigned ph = atomicAdd(&g_bar_phase, 0u);   // read BEFORE first arrive

    // init state + loss accumulators
    for (int i = blockIdx.x * NTHR + tid; i < NB * HD; i += NBLK * NTHR) {
        g_h0[0][i] = 0.f; g_h1[0][i] = 0.f;
        g_c0[i] = 0.f;    g_c1[i] = 0.f;
    }
    if (blockIdx.x == 0 && tid == 0) {
        g_cls_sum = 0.f; g_bbox_sum = 0.f; g_correct = 0;
    }
    grid_bar(ph);

    for (int t = 0; t < SEQ; ++t) {
        int p = t & 1;
        // layer 0: x = data[:, t, :], h = h0[p] -> h0[1-p]
        lstm_tile(data + (size_t)t * CH, SEQ * CH, CH, Wih0,
                  g_h0[p], Whh0, b0, g_c0, g_h0[1 - p], As, Bs);
        grid_bar(ph);
        // layer 1: x = h0[1-p], h = h1[p] -> h1[1-p]
        lstm_tile(g_h0[1 - p], HD, HD, Wih1,
                  g_h1[p], Whh1, b1, g_c1, g_h1[1 - p], As, Bs);
        grid_bar(ph);
    }

    // heads + loss: final hidden state is g_h1[0] (t=255 wrote buffer 0)
    {
        float* hrow = &As[0][0];   // 512 floats
        float* cls  = &Bs[0][0];   // 40 floats
        for (int r = 0; r < 8; ++r) {
            int n = blockIdx.x * 8 + r;
            for (int j = tid; j < HD; j += NTHR)
                hrow[j] = g_h1[0][(size_t)n * HD + j];
            __syncthreads();
            if (tid < NCLS) {
                float s = bcls[tid];
                const float* w = Wcls + (size_t)tid * HD;
                #pragma unroll 8
                for (int j = 0; j < HD; ++j) s += hrow[j] * w[j];
                cls[tid] = s;
            } else if (tid < NCLS + 2) {
                int pp = tid - NCLS;
                float s = bbbox[pp];
                const float* w = Wbbox + (size_t)pp * HD;
                #pragma unroll 8
                for (int j = 0; j < HD; ++j) s += hrow[j] * w[j];
                float tg = props[n * 2 + pp] * (1.0f / (float)SEQ);
                float d  = fabsf(s - tg);
                float sl = (d < 1.f) ? 0.5f * d * d : d - 0.5f;
                atomicAdd(&g_bbox_sum, sl);
            }
            __syncthreads();
            if (tid == 0) {
                float m = cls[0]; int am = 0;
                for (int k = 1; k < NCLS; ++k)
                    if (cls[k] > m) { m = cls[k]; am = k; }
                float se = 0.f;
                for (int k = 0; k < NCLS; ++k) se += expf(cls[k] - m);
                float lse = m + logf(se);
                int lbl = labels[n * 2];
                atomicAdd(&g_cls_sum, -(cls[lbl] - lse));
                if (am == lbl) atomicAdd(&g_correct, 1);
            }
            __syncthreads();
        }
    }
    grid_bar(ph);

    if (blockIdx.x == 0 && tid == 0) {
        out[0] = (g_cls_sum / (float)NB) / (1.0f + (float)g_correct);
        out[1] = (g_bbox_sum / (float)(NB * 2)) * 10.0f;
    }
}

// ---------------- launch: ONE graph node -------------------------------------
extern "C" void kernel_launch(void* const* d_in, const int* in_sizes, int n_in,
                              void* d_out, int out_size) {
    const float* data   = (const float*)d_in[0];
    const int*   labels = (const int*)  d_in[1];
    const float* props  = (const float*)d_in[2];
    const float* Wih0   = (const float*)d_in[3];
    const float* Whh0   = (const float*)d_in[4];
    const float* b0     = (const float*)d_in[5];
    const float* Wih1   = (const float*)d_in[6];
    const float* Whh1   = (const float*)d_in[7];
    const float* b1     = (const float*)d_in[8];
    const float* Wcls   = (const float*)d_in[9];
    const float* bcls   = (const float*)d_in[10];
    const float* Wbbox  = (const float*)d_in[11];
    const float* bbbox  = (const float*)d_in[12];
    float* out = (float*)d_out;

    rlstm_persistent<<<NBLK, NTHR>>>(data, labels, props,
                                     Wih0, Whh0, b0, Wih1, Whh1, b1,
                                     Wcls, bcls, Wbbox, bbbox, out);
}

// round 6
// speedup vs baseline: 1.4187x; 1.4187x over previous
#include <cuda_runtime.h>
#include <math.h>
#include <stdint.h>

#define HD    512
#define GATES 2048
#define NB    1024
#define SEQ   256
#define CH    128
#define NCLS  40
#define NBLK  128
#define NTHR  256

// smem: 4 tiles (Ahi, Alo, Bhi, Blo), each 128 rows x 36 floats (stride-36 pad)
#define TSTRIDE 36
#define TILE_FLOATS (128 * TSTRIDE)          // 4608
#define SMEM_SZ (4 * TILE_FLOATS * 4)        // 73728 bytes

// ---------------- persistent device scratch ---------------------------------
__device__ float g_h0[2][NB * HD];
__device__ float g_c0[NB * HD];
__device__ float g_h1[2][NB * HD];
__device__ float g_c1[NB * HD];
__device__ float g_cls_sum;
__device__ float g_bbox_sum;
__device__ int   g_correct;
__device__ unsigned g_bar_count;
__device__ unsigned g_bar_phase;   // monotonic across replays

// ---------------- helpers ----------------------------------------------------
__device__ __forceinline__ float f2tf32(float x) {
    float y; asm("cvt.rna.tf32.f32 %0, %1;" : "=f"(y) : "f"(x)); return y;
}

__device__ __forceinline__ void mma_tf32(float* d, const uint32_t* a, const uint32_t* b) {
    asm volatile(
        "mma.sync.aligned.m16n8k8.row.col.f32.tf32.tf32.f32 "
        "{%0,%1,%2,%3}, {%4,%5,%6,%7}, {%8,%9}, {%0,%1,%2,%3};"
        : "+f"(d[0]), "+f"(d[1]), "+f"(d[2]), "+f"(d[3])
        : "r"(a[0]), "r"(a[1]), "r"(a[2]), "r"(a[3]), "r"(b[0]), "r"(b[1]));
}

// ---------------- software grid barrier --------------------------------------
__device__ __forceinline__ void grid_bar(unsigned& my_phase) {
    __syncthreads();
    if (threadIdx.x == 0) {
        __threadfence();
        unsigned old = atomicAdd(&g_bar_count, 1u);
        if (old == NBLK - 1) {
            g_bar_count = 0;
            __threadfence();
            atomicExch(&g_bar_phase, my_phase + 1u);
        } else {
            while (atomicAdd(&g_bar_phase, 0u) <= my_phase) __nanosleep(64);
        }
        __threadfence();
    }
    my_phase++;
    __syncthreads();
}

// ---------------- fill one 32-K chunk (A + B, hi/lo tf32 split) --------------
// A tile: rows = batch rows [row0, +128), cols = k0..k0+31
// B tile: row c = permuted gate row: gate=(c&3), jj=j0+(c>>2)
__device__ __forceinline__ void fill_tiles(
    const float* __restrict__ A, int astr,
    const float* __restrict__ B, int bstr, int k0,
    int row0, int j0, float* sm, int tid)
{
    float* aHi = sm;
    float* aLo = sm + TILE_FLOATS;
    float* bHi = sm + 2 * TILE_FLOATS;
    float* bLo = sm + 3 * TILE_FLOATS;
    #pragma unroll
    for (int l = 0; l < 4; ++l) {
        int idx = tid + l * 256;
        int r = idx >> 3, fc = idx & 7;
        int so = r * TSTRIDE + fc * 4;

        float4 v = *reinterpret_cast<const float4*>(&A[(size_t)(row0 + r) * astr + k0 + fc * 4]);
        float4 hi, lo;
        hi.x = f2tf32(v.x); lo.x = f2tf32(v.x - hi.x);
        hi.y = f2tf32(v.y); lo.y = f2tf32(v.y - hi.y);
        hi.z = f2tf32(v.z); lo.z = f2tf32(v.z - hi.z);
        hi.w = f2tf32(v.w); lo.w = f2tf32(v.w - hi.w);
        *reinterpret_cast<float4*>(&aHi[so]) = hi;
        *reinterpret_cast<float4*>(&aLo[so]) = lo;

        int grow = (r & 3) * HD + j0 + (r >> 2);
        float4 w = *reinterpret_cast<const float4*>(&B[(size_t)grow * bstr + k0 + fc * 4]);
        float4 whi, wlo;
        whi.x = f2tf32(w.x); wlo.x = f2tf32(w.x - whi.x);
        whi.y = f2tf32(w.y); wlo.y = f2tf32(w.y - whi.y);
        whi.z = f2tf32(w.z); wlo.z = f2tf32(w.z - whi.z);
        whi.w = f2tf32(w.w); wlo.w = f2tf32(w.w - whi.w);
        *reinterpret_cast<float4*>(&bHi[so]) = whi;
        *reinterpret_cast<float4*>(&bLo[so]) = wlo;
    }
}

// ---------------- one LSTM layer-step (mma.sync GEMM + fused cell) -----------
__device__ __forceinline__ void lstm_step(
    const float* __restrict__ X, int xstr, int Kx,
    const float* __restrict__ Wih,
    const float* __restrict__ Hprev,
    const float* __restrict__ Whh,
    const float* __restrict__ bias,
    float* __restrict__ cbuf, float* __restrict__ hout,
    float* sm)
{
    const int tid  = threadIdx.x;
    const int lane = tid & 31;
    const int w    = tid >> 5;
    const int m0w  = (w >> 2) * 64;        // warp m-offset (0 or 64)
    const int n0w  = (w & 3) * 32;         // warp n-offset (0,32,64,96)
    const int tr   = lane >> 2;
    const int tc   = lane & 3;
    const int row0 = (blockIdx.x >> 4) * 128;
    const int j0   = (blockIdx.x & 15) * 32;
    const int nch0 = Kx / 32;
    const int ntot = nch0 + HD / 32;

    const uint32_t* aHiU = (const uint32_t*)sm;
    const uint32_t* aLoU = aHiU + TILE_FLOATS;
    const uint32_t* bHiU = aHiU + 2 * TILE_FLOATS;
    const uint32_t* bLoU = aHiU + 3 * TILE_FLOATS;

    float d[4][4][4];
    #pragma unroll
    for (int mf = 0; mf < 4; ++mf)
        #pragma unroll
        for (int nf = 0; nf < 4; ++nf)
            #pragma unroll
            for (int q = 0; q < 4; ++q) d[mf][nf][q] = 0.f;

    for (int kk = 0; kk < ntot; ++kk) {
        const float* A; int astr; const float* B; int bstr; int k0;
        if (kk < nch0) { A = X;     astr = xstr; B = Wih; bstr = Kx; k0 = kk * 32; }
        else           { A = Hprev; astr = HD;   B = Whh; bstr = HD; k0 = (kk - nch0) * 32; }

        __syncthreads();   // previous chunk's fragment reads done
        fill_tiles(A, astr, B, bstr, k0, row0, j0, sm, tid);
        __syncthreads();

        #pragma unroll
        for (int k8 = 0; k8 < 4; ++k8) {
            const int kb = k8 * 8;
            uint32_t ah[4][4], al[4][4];
            #pragma unroll
            for (int mf = 0; mf < 4; ++mf) {
                int rb = (m0w + mf * 16 + tr) * TSTRIDE + kb + tc;
                ah[mf][0] = aHiU[rb];
                ah[mf][1] = aHiU[rb + 8 * TSTRIDE];
                ah[mf][2] = aHiU[rb + 4];
                ah[mf][3] = aHiU[rb + 8 * TSTRIDE + 4];
                al[mf][0] = aLoU[rb];
                al[mf][1] = aLoU[rb + 8 * TSTRIDE];
                al[mf][2] = aLoU[rb + 4];
                al[mf][3] = aLoU[rb + 8 * TSTRIDE + 4];
            }
            #pragma unroll
            for (int nf = 0; nf < 4; ++nf) {
                int cb = (n0w + nf * 8 + tr) * TSTRIDE + kb + tc;
                uint32_t bh[2], bl[2];
                bh[0] = bHiU[cb];  bh[1] = bHiU[cb + 4];
                bl[0] = bLoU[cb];  bl[1] = bLoU[cb + 4];
                #pragma unroll
                for (int mf = 0; mf < 4; ++mf) {
                    mma_tf32(d[mf][nf], ah[mf], bh);
                    mma_tf32(d[mf][nf], ah[mf], bl);
                    mma_tf32(d[mf][nf], al[mf], bh);
                }
            }
        }
    }

    // epilogue: gate exchange (partner lane^1 holds the other 2 gates of same jj)
    #pragma unroll
    for (int mf = 0; mf < 4; ++mf) {
        #pragma unroll
        for (int nf = 0; nf < 4; ++nf) {
            float v0 = d[mf][nf][0], v1 = d[mf][nf][1];
            float v2 = d[mf][nf][2], v3 = d[mf][nf][3];
            float r0 = __shfl_xor_sync(0xffffffffu, v0, 1);
            float r1 = __shfl_xor_sync(0xffffffffu, v1, 1);
            float r2 = __shfl_xor_sync(0xffffffffu, v2, 1);
            float r3 = __shfl_xor_sync(0xffffffffu, v3, 1);
            if ((lane & 1) == 0) {
                int col = n0w + nf * 8 + tc * 2;       // col&3==0: this lane has i,f
                int jj  = j0 + (col >> 2);
                int m   = row0 + m0w + mf * 16 + tr;
                float b0v = bias[jj], b1v = bias[HD + jj];
                float b2v = bias[2 * HD + jj], b3v = bias[3 * HD + jj];
                // row m
                {
                    float gi = v0 + b0v, gf = v1 + b1v, gg = r0 + b2v, go = r1 + b3v;
                    float si = 1.f / (1.f + expf(-gi));
                    float sf = 1.f / (1.f + expf(-gf));
                    float so = 1.f / (1.f + expf(-go));
                    size_t ix = (size_t)m * HD + jj;
                    float cv = sf * cbuf[ix] + si * tanhf(gg);
                    cbuf[ix] = cv;
                    hout[ix] = so * tanhf(cv);
                }
                // row m+8
                {
                    float gi = v2 + b0v, gf = v3 + b1v, gg = r2 + b2v, go = r3 + b3v;
                    float si = 1.f / (1.f + expf(-gi));
                    float sf = 1.f / (1.f + expf(-gf));
                    float so = 1.f / (1.f + expf(-go));
                    size_t ix = (size_t)(m + 8) * HD + jj;
                    float cv = sf * cbuf[ix] + si * tanhf(gg);
                    cbuf[ix] = cv;
                    hout[ix] = so * tanhf(cv);
                }
            }
        }
    }
}

// ---------------- whole network, one persistent kernel -----------------------
__global__ __launch_bounds__(NTHR, 1)
void rlstm_persistent(const float* __restrict__ data,
                      const int*   __restrict__ labels,
                      const float* __restrict__ props,
                      const float* __restrict__ Wih0, const float* __restrict__ Whh0,
                      const float* __restrict__ b0,
                      const float* __restrict__ Wih1, const float* __restrict__ Whh1,
                      const float* __restrict__ b1,
                      const float* __restrict__ Wcls, const float* __restrict__ bcls,
                      const float* __restrict__ Wbbox, const float* __restrict__ bbbox,
                      float* __restrict__ out)
{
    extern __shared__ float sm[];
    const int tid = threadIdx.x;
    unsigned ph = atomicAdd(&g_bar_phase, 0u);   // read BEFORE first arrive

    // init state + loss accumulators
    for (int i = blockIdx.x * NTHR + tid; i < NB * HD; i += NBLK * NTHR) {
        g_h0[0][i] = 0.f; g_h1[0][i] = 0.f;
        g_c0[i] = 0.f;    g_c1[i] = 0.f;
    }
    if (blockIdx.x == 0 && tid == 0) {
        g_cls_sum = 0.f; g_bbox_sum = 0.f; g_correct = 0;
    }
    grid_bar(ph);

    for (int t = 0; t < SEQ; ++t) {
        int p = t & 1;
        lstm_step(data + (size_t)t * CH, SEQ * CH, CH, Wih0,
                  g_h0[p], Whh0, b0, g_c0, g_h0[1 - p], sm);
        grid_bar(ph);
        lstm_step(g_h0[1 - p], HD, HD, Wih1,
                  g_h1[p], Whh1, b1, g_c1, g_h1[1 - p], sm);
        grid_bar(ph);
    }

    // heads + loss on final hidden state g_h1[0]
    {
        float* hrow = sm;          // 512 floats
        float* cls  = sm + HD;     // 40 floats
        for (int r = 0; r < 8; ++r) {
            int n = blockIdx.x * 8 + r;
            for (int j = tid; j < HD; j += NTHR)
                hrow[j] = g_h1[0][(size_t)n * HD + j];
            __syncthreads();
            if (tid < NCLS) {
                float s = bcls[tid];
                const float* wp = Wcls + (size_t)tid * HD;
                #pragma unroll 8
                for (int j = 0; j < HD; ++j) s += hrow[j] * wp[j];
                cls[tid] = s;
            } else if (tid < NCLS + 2) {
                int pp = tid - NCLS;
                float s = bbbox[pp];
                const float* wp = Wbbox + (size_t)pp * HD;
                #pragma unroll 8
                for (int j = 0; j < HD; ++j) s += hrow[j] * wp[j];
                float tg = props[n * 2 + pp] * (1.0f / (float)SEQ);
                float dd = fabsf(s - tg);
                float sl = (dd < 1.f) ? 0.5f * dd * dd : dd - 0.5f;
                atomicAdd(&g_bbox_sum, sl);
            }
            __syncthreads();
            if (tid == 0) {
                float mx = cls[0]; int am = 0;
                for (int k = 1; k < NCLS; ++k)
                    if (cls[k] > mx) { mx = cls[k]; am = k; }
                float se = 0.f;
                for (int k = 0; k < NCLS; ++k) se += expf(cls[k] - mx);
                float lse = mx + logf(se);
                int lbl = labels[n * 2];
                atomicAdd(&g_cls_sum, -(cls[lbl] - lse));
                if (am == lbl) atomicAdd(&g_correct, 1);
            }
            __syncthreads();
        }
    }
    grid_bar(ph);

    if (blockIdx.x == 0 && tid == 0) {
        out[0] = (g_cls_sum / (float)NB) / (1.0f + (float)g_correct);
        out[1] = (g_bbox_sum / (float)(NB * 2)) * 10.0f;
    }
}

// ---------------- launch: ONE graph node -------------------------------------
extern "C" void kernel_launch(void* const* d_in, const int* in_sizes, int n_in,
                              void* d_out, int out_size) {
    const float* data   = (const float*)d_in[0];
    const int*   labels = (const int*)  d_in[1];
    const float* props  = (const float*)d_in[2];
    const float* Wih0   = (const float*)d_in[3];
    const float* Whh0   = (const float*)d_in[4];
    const float* b0     = (const float*)d_in[5];
    const float* Wih1   = (const float*)d_in[6];
    const float* Whh1   = (const float*)d_in[7];
    const float* b1     = (const float*)d_in[8];
    const float* Wcls   = (const float*)d_in[9];
    const float* bcls   = (const float*)d_in[10];
    const float* Wbbox  = (const float*)d_in[11];
    const float* bbbox  = (const float*)d_in[12];
    float* out = (float*)d_out;

    cudaFuncSetAttribute(rlstm_persistent,
                         cudaFuncAttributeMaxDynamicSharedMemorySize, SMEM_SZ);
    rlstm_persistent<<<NBLK, NTHR, SMEM_SZ>>>(data, labels, props,
                                              Wih0, Whh0, b0, Wih1, Whh1, b1,
                                              Wcls, bcls, Wbbox, bbbox, out);
}

// round 7
// speedup vs baseline: 1.5535x; 1.0950x over previous
#include <cuda_runtime.h>
#include <math.h>
#include <stdint.h>

#define HD    512
#define GATES 2048
#define NB    1024
#define SEQ   256
#define CH    128
#define NCLS  40
#define NBLK  128
#define NTHR  256

#define TSTRIDE 36
#define TILE_FLOATS (128 * TSTRIDE)              // 4608
#define STAGE_FLOATS (4 * TILE_FLOATS)           // aHi,aLo,bHi,bLo = 18432
#define SMEM_SZ (2 * STAGE_FLOATS * 4)           // 147456 bytes

// precomputed hi/lo split weights, packed per (layer, jt, chunk) tile [128][32]
#define W0_NCH 20                                 // 4 x-chunks + 16 h-chunks
#define W1_NCH 32                                 // 16 + 16
#define W0_TILES (16 * W0_NCH)                    // 320
#define W1_TILES (16 * W1_NCH)                    // 512
#define WTILE 4096
#define WN ((W0_TILES + W1_TILES) * WTILE)        // 3,407,872 floats

// ---------------- persistent device scratch ---------------------------------
__device__ float g_whi[WN];
__device__ float g_wlo[WN];
__device__ float g_h0[2][NB * HD];
__device__ float g_c0[NB * HD];
__device__ float g_h1[2][NB * HD];
__device__ float g_c1[NB * HD];
__device__ float g_cls_sum;
__device__ float g_bbox_sum;
__device__ int   g_correct;
__device__ unsigned g_bar_count;
__device__ unsigned g_bar_phase;   // monotonic across replays

// ---------------- helpers ----------------------------------------------------
__device__ __forceinline__ float f2tf32(float x) {
    float y; asm("cvt.rna.tf32.f32 %0, %1;" : "=f"(y) : "f"(x)); return y;
}
__device__ __forceinline__ uint32_t smem_u32(const void* p) {
    uint32_t a;
    asm("{ .reg .u64 t; cvta.to.shared.u64 t, %1; cvt.u32.u64 %0, t; }"
        : "=r"(a) : "l"(p));
    return a;
}
__device__ __forceinline__ void mma_tf32(float* d, const uint32_t* a, const uint32_t* b) {
    asm volatile(
        "mma.sync.aligned.m16n8k8.row.col.f32.tf32.tf32.f32 "
        "{%0,%1,%2,%3}, {%4,%5,%6,%7}, {%8,%9}, {%0,%1,%2,%3};"
        : "+f"(d[0]), "+f"(d[1]), "+f"(d[2]), "+f"(d[3])
        : "r"(a[0]), "r"(a[1]), "r"(a[2]), "r"(a[3]), "r"(b[0]), "r"(b[1]));
}
#define CP16(dst, src) asm volatile("cp.async.cg.shared.global [%0], [%1], 16;" :: "r"(dst), "l"(src) : "memory")
#define CP_COMMIT()    asm volatile("cp.async.commit_group;" ::: "memory")
#define CP_WAIT1()     asm volatile("cp.async.wait_group 1;" ::: "memory")
#define CP_WAIT0()     asm volatile("cp.async.wait_group 0;" ::: "memory")

// ---------------- software grid barrier --------------------------------------
__device__ __forceinline__ void grid_bar(unsigned& my_phase) {
    __syncthreads();
    if (threadIdx.x == 0) {
        __threadfence();
        unsigned old = atomicAdd(&g_bar_count, 1u);
        if (old == NBLK - 1) {
            g_bar_count = 0;
            __threadfence();
            atomicExch(&g_bar_phase, my_phase + 1u);
        } else {
            while (atomicAdd(&g_bar_phase, 0u) <= my_phase) __nanosleep(64);
        }
        __threadfence();
    }
    my_phase++;
    __syncthreads();
}

// ---------------- one LSTM layer-step (pipelined mma.sync + fused cell) ------
__device__ __forceinline__ void lstm_step(
    const float* __restrict__ X, int xstr, int Kx,
    const float* __restrict__ Hprev,
    int wbase,                                  // tile index base for (layer, jt)
    const float* __restrict__ bias,
    float* __restrict__ cbuf, float* __restrict__ hout,
    float* sm, uint32_t su)
{
    const int tid  = threadIdx.x;
    const int lane = tid & 31;
    const int w    = tid >> 5;
    const int m0w  = (w >> 2) * 64;
    const int n0w  = (w & 3) * 32;
    const int tr   = lane >> 2;
    const int tc   = lane & 3;
    const int row0 = (blockIdx.x >> 4) * 128;
    const int j0   = (blockIdx.x & 15) * 32;
    const int nch0 = Kx / 32;
    const int ntot = nch0 + HD / 32;

    float d[4][4][4];
    #pragma unroll
    for (int mf = 0; mf < 4; ++mf)
        #pragma unroll
        for (int nf = 0; nf < 4; ++nf)
            #pragma unroll
            for (int q = 0; q < 4; ++q) d[mf][nf][q] = 0.f;

    float4 a4[4];

    // ---- local helpers (inlined) ----
    #define LDG_A(kk_)  do {                                                   \
        const float* Ap; int astr_, k0_;                                       \
        if ((kk_) < nch0) { Ap = X;     astr_ = xstr; k0_ = (kk_) * 32; }      \
        else              { Ap = Hprev; astr_ = HD;   k0_ = ((kk_) - nch0) * 32; } \
        _Pragma("unroll")                                                      \
        for (int l = 0; l < 4; ++l) {                                          \
            int idx = tid + l * 256; int r = idx >> 3, fc = idx & 7;           \
            a4[l] = *reinterpret_cast<const float4*>(                          \
                &Ap[(size_t)(row0 + r) * astr_ + k0_ + fc * 4]);               \
        } } while (0)

    #define ST_A(s_)  do {                                                     \
        float* aHi = sm + (s_) * STAGE_FLOATS;                                 \
        float* aLo = aHi + TILE_FLOATS;                                        \
        _Pragma("unroll")                                                      \
        for (int l = 0; l < 4; ++l) {                                          \
            int idx = tid + l * 256; int r = idx >> 3, fc = idx & 7;           \
            int so = r * TSTRIDE + fc * 4;                                     \
            float4 v = a4[l], hi, lo;                                          \
            hi.x = f2tf32(v.x); lo.x = f2tf32(v.x - hi.x);                     \
            hi.y = f2tf32(v.y); lo.y = f2tf32(v.y - hi.y);                     \
            hi.z = f2tf32(v.z); lo.z = f2tf32(v.z - hi.z);                     \
            hi.w = f2tf32(v.w); lo.w = f2tf32(v.w - hi.w);                     \
            *reinterpret_cast<float4*>(&aHi[so]) = hi;                         \
            *reinterpret_cast<float4*>(&aLo[so]) = lo;                         \
        } } while (0)

    #define CP_B(kk_, s_)  do {                                                \
        const float* srcHi = g_whi + (size_t)(wbase + (kk_)) * WTILE;          \
        const float* srcLo = g_wlo + (size_t)(wbase + (kk_)) * WTILE;          \
        uint32_t bHiA = su + ((s_) * STAGE_FLOATS + 2 * TILE_FLOATS) * 4u;     \
        uint32_t bLoA = su + ((s_) * STAGE_FLOATS + 3 * TILE_FLOATS) * 4u;     \
        _Pragma("unroll")                                                      \
        for (int l = 0; l < 4; ++l) {                                          \
            int idx = tid + l * 256; int r = idx >> 3, p = idx & 7;            \
            uint32_t doff = (uint32_t)(r * (TSTRIDE * 4) + p * 16);            \
            int soff = r * 32 + p * 4;                                         \
            CP16(bHiA + doff, srcHi + soff);                                   \
            CP16(bLoA + doff, srcLo + soff);                                   \
        } } while (0)

    // ---- prologue: stage chunk 0 into buffer 0 ----
    CP_B(0, 0); CP_COMMIT();
    LDG_A(0);
    ST_A(0);

    for (int kk = 0; kk < ntot; ++kk) {
        const int s = kk & 1;
        const bool pf = (kk + 1 < ntot);
        if (pf) LDG_A(kk + 1);                 // long-latency LDG starts now
        __syncthreads();                        // all MMA(kk-1) readers done
        if (pf) { CP_B(kk + 1, 1 - s); CP_COMMIT(); }
        if (pf) CP_WAIT1(); else CP_WAIT0();    // B(kk) landed (own thread)
        __syncthreads();                        // B(kk)+A(kk) visible to all

        const uint32_t* aHiU = (const uint32_t*)(sm + s * STAGE_FLOATS);
        const uint32_t* aLoU = aHiU + TILE_FLOATS;
        const uint32_t* bHiU = aHiU + 2 * TILE_FLOATS;
        const uint32_t* bLoU = aHiU + 3 * TILE_FLOATS;

        #pragma unroll
        for (int k8 = 0; k8 < 4; ++k8) {
            const int kb = k8 * 8;
            uint32_t ah[4][4], al[4][4];
            #pragma unroll
            for (int mf = 0; mf < 4; ++mf) {
                int rb = (m0w + mf * 16 + tr) * TSTRIDE + kb + tc;
                ah[mf][0] = aHiU[rb];
                ah[mf][1] = aHiU[rb + 8 * TSTRIDE];
                ah[mf][2] = aHiU[rb + 4];
                ah[mf][3] = aHiU[rb + 8 * TSTRIDE + 4];
                al[mf][0] = aLoU[rb];
                al[mf][1] = aLoU[rb + 8 * TSTRIDE];
                al[mf][2] = aLoU[rb + 4];
                al[mf][3] = aLoU[rb + 8 * TSTRIDE + 4];
            }
            #pragma unroll
            for (int nf = 0; nf < 4; ++nf) {
                int cb = (n0w + nf * 8 + tr) * TSTRIDE + kb + tc;
                uint32_t bh[2], bl[2];
                bh[0] = bHiU[cb];  bh[1] = bHiU[cb + 4];
                bl[0] = bLoU[cb];  bl[1] = bLoU[cb + 4];
                #pragma unroll
                for (int mf = 0; mf < 4; ++mf) {
                    mma_tf32(d[mf][nf], ah[mf], bh);
                    mma_tf32(d[mf][nf], ah[mf], bl);
                    mma_tf32(d[mf][nf], al[mf], bh);
                }
            }
        }

        if (pf) ST_A(1 - s);                    // convert+store A(kk+1)
    }

    #undef LDG_A
    #undef ST_A
    #undef CP_B

    // ---- epilogue: gate exchange + fused cell pointwise ----
    #pragma unroll
    for (int mf = 0; mf < 4; ++mf) {
        #pragma unroll
        for (int nf = 0; nf < 4; ++nf) {
            float v0 = d[mf][nf][0], v1 = d[mf][nf][1];
            float v2 = d[mf][nf][2], v3 = d[mf][nf][3];
            float r0 = __shfl_xor_sync(0xffffffffu, v0, 1);
            float r1 = __shfl_xor_sync(0xffffffffu, v1, 1);
            float r2 = __shfl_xor_sync(0xffffffffu, v2, 1);
            float r3 = __shfl_xor_sync(0xffffffffu, v3, 1);
            if ((lane & 1) == 0) {
                int col = n0w + nf * 8 + tc * 2;
                int jj  = j0 + (col >> 2);
                int m   = row0 + m0w + mf * 16 + tr;
                float b0v = bias[jj], b1v = bias[HD + jj];
                float b2v = bias[2 * HD + jj], b3v = bias[3 * HD + jj];
                {
                    float gi = v0 + b0v, gf = v1 + b1v, gg = r0 + b2v, go = r1 + b3v;
                    float si = 1.f / (1.f + expf(-gi));
                    float sf = 1.f / (1.f + expf(-gf));
                    float so = 1.f / (1.f + expf(-go));
                    size_t ix = (size_t)m * HD + jj;
                    float cv = sf * cbuf[ix] + si * tanhf(gg);
                    cbuf[ix] = cv;
                    hout[ix] = so * tanhf(cv);
                }
                {
                    float gi = v2 + b0v, gf = v3 + b1v, gg = r2 + b2v, go = r3 + b3v;
                    float si = 1.f / (1.f + expf(-gi));
                    float sf = 1.f / (1.f + expf(-gf));
                    float so = 1.f / (1.f + expf(-go));
                    size_t ix = (size_t)(m + 8) * HD + jj;
                    float cv = sf * cbuf[ix] + si * tanhf(gg);
                    cbuf[ix] = cv;
                    hout[ix] = so * tanhf(cv);
                }
            }
        }
    }
}

// ---------------- whole network, one persistent kernel -----------------------
__global__ __launch_bounds__(NTHR, 1)
void rlstm_persistent(const float* __restrict__ data,
                      const int*   __restrict__ labels,
                      const float* __restrict__ props,
                      const float* __restrict__ Wih0, const float* __restrict__ Whh0,
                      const float* __restrict__ b0,
                      const float* __restrict__ Wih1, const float* __restrict__ Whh1,
                      const float* __restrict__ b1,
                      const float* __restrict__ Wcls, const float* __restrict__ bcls,
                      const float* __restrict__ Wbbox, const float* __restrict__ bbbox,
                      float* __restrict__ out)
{
    extern __shared__ float sm[];
    uint32_t su = smem_u32(sm);
    const int tid = threadIdx.x;
    unsigned ph = atomicAdd(&g_bar_phase, 0u);   // read BEFORE first arrive

    // init state + loss accumulators
    for (int i = blockIdx.x * NTHR + tid; i < NB * HD; i += NBLK * NTHR) {
        g_h0[0][i] = 0.f; g_h1[0][i] = 0.f;
        g_c0[i] = 0.f;    g_c1[i] = 0.f;
    }
    if (blockIdx.x == 0 && tid == 0) {
        g_cls_sum = 0.f; g_bbox_sum = 0.f; g_correct = 0;
    }
    // precompute hi/lo-split weights in packed (jt, chunk) tile order
    for (int i = blockIdx.x * NTHR + tid; i < WN; i += NBLK * NTHR) {
        int tile = i >> 12, e = i & 4095;
        int r = e >> 5, k = e & 31;
        int jt, kk;
        const float* B; int bstr, k0;
        if (tile < W0_TILES) {
            jt = tile / W0_NCH; kk = tile % W0_NCH;
            if (kk < 4) { B = Wih0; bstr = CH; k0 = kk * 32; }
            else        { B = Whh0; bstr = HD; k0 = (kk - 4) * 32; }
        } else {
            int t2 = tile - W0_TILES;
            jt = t2 / W1_NCH; kk = t2 % W1_NCH;
            if (kk < 16) { B = Wih1; bstr = HD; k0 = kk * 32; }
            else         { B = Whh1; bstr = HD; k0 = (kk - 16) * 32; }
        }
        int grow = (r & 3) * HD + jt * 32 + (r >> 2);
        float v = B[(size_t)grow * bstr + k0 + k];
        float hi = f2tf32(v);
        g_whi[i] = hi;
        g_wlo[i] = f2tf32(v - hi);
    }
    grid_bar(ph);

    const int jt = blockIdx.x & 15;
    const int wbase0 = jt * W0_NCH;
    const int wbase1 = W0_TILES + jt * W1_NCH;

    for (int t = 0; t < SEQ; ++t) {
        int p = t & 1;
        lstm_step(data + (size_t)t * CH, SEQ * CH, CH,
                  g_h0[p], wbase0, b0, g_c0, g_h0[1 - p], sm, su);
        grid_bar(ph);
        lstm_step(g_h0[1 - p], HD, HD,
                  g_h1[p], wbase1, b1, g_c1, g_h1[1 - p], sm, su);
        grid_bar(ph);
    }

    // heads + loss on final hidden state g_h1[0]
    {
        float* hrow = sm;
        float* cls  = sm + HD;
        for (int r = 0; r < 8; ++r) {
            int n = blockIdx.x * 8 + r;
            for (int j = tid; j < HD; j += NTHR)
                hrow[j] = g_h1[0][(size_t)n * HD + j];
            __syncthreads();
            if (tid < NCLS) {
                float s = bcls[tid];
                const float* wp = Wcls + (size_t)tid * HD;
                #pragma unroll 8
                for (int j = 0; j < HD; ++j) s += hrow[j] * wp[j];
                cls[tid] = s;
            } else if (tid < NCLS + 2) {
                int pp = tid - NCLS;
                float s = bbbox[pp];
                const float* wp = Wbbox + (size_t)pp * HD;
                #pragma unroll 8
                for (int j = 0; j < HD; ++j) s += hrow[j] * wp[j];
                float tg = props[n * 2 + pp] * (1.0f / (float)SEQ);
                float dd = fabsf(s - tg);
                float sl = (dd < 1.f) ? 0.5f * dd * dd : dd - 0.5f;
                atomicAdd(&g_bbox_sum, sl);
            }
            __syncthreads();
            if (tid == 0) {
                float mx = cls[0]; int am = 0;
                for (int k = 1; k < NCLS; ++k)
                    if (cls[k] > mx) { mx = cls[k]; am = k; }
                float se = 0.f;
                for (int k = 0; k < NCLS; ++k) se += expf(cls[k] - mx);
                float lse = mx + logf(se);
                int lbl = labels[n * 2];
                atomicAdd(&g_cls_sum, -(cls[lbl] - lse));
                if (am == lbl) atomicAdd(&g_correct, 1);
            }
            __syncthreads();
        }
    }
    grid_bar(ph);

    if (blockIdx.x == 0 && tid == 0) {
        out[0] = (g_cls_sum / (float)NB) / (1.0f + (float)g_correct);
        out[1] = (g_bbox_sum / (float)(NB * 2)) * 10.0f;
    }
}

// ---------------- launch: ONE graph node -------------------------------------
extern "C" void kernel_launch(void* const* d_in, const int* in_sizes, int n_in,
                              void* d_out, int out_size) {
    const float* data   = (const float*)d_in[0];
    const int*   labels = (const int*)  d_in[1];
    const float* props  = (const float*)d_in[2];
    const float* Wih0   = (const float*)d_in[3];
    const float* Whh0   = (const float*)d_in[4];
    const float* b0     = (const float*)d_in[5];
    const float* Wih1   = (const float*)d_in[6];
    const float* Whh1   = (const float*)d_in[7];
    const float* b1     = (const float*)d_in[8];
    const float* Wcls   = (const float*)d_in[9];
    const float* bcls   = (const float*)d_in[10];
    const float* Wbbox  = (const float*)d_in[11];
    const float* bbbox  = (const float*)d_in[12];
    float* out = (float*)d_out;

    cudaFuncSetAttribute(rlstm_persistent,
                         cudaFuncAttributeMaxDynamicSharedMemorySize, SMEM_SZ);
    rlstm_persistent<<<NBLK, NTHR, SMEM_SZ>>>(data, labels, props,
                                              Wih0, Whh0, b0, Wih1, Whh1, b1,
                                              Wcls, bcls, Wbbox, bbbox, out);
}

// round 8
// speedup vs baseline: 2.3129x; 1.4888x over previous
#include <cuda_runtime.h>
#include <cuda_bf16.h>
#include <math.h>
#include <stdint.h>

#define HD    512
#define GATES 2048
#define NB    1024
#define SEQ   256
#define CH    128
#define NCLS  40
#define NBLK  128
#define NTHR  256

// smem stage (u32 units): aHi | aLo | bHi | bLo, each 128 rows x 20 u32 (40 bf16, pad)
#define RSTRIDE 20                    // u32 per row (16 data + 4 pad)
#define TILE_U32 (128 * RSTRIDE)      // 2560
#define STAGE_U32 (4 * TILE_U32)      // 10240
#define SMEM_SZ (2 * STAGE_U32 * 4)   // 81920 bytes

// precomputed hi/lo bf16 weights, packed per (layer, jt, chunk) tile [128][32]
#define W0_NCH 20
#define W1_NCH 32
#define W0_TILES (16 * W0_NCH)
#define W1_TILES (16 * W1_NCH)
#define WTILE 4096
#define WN ((W0_TILES + W1_TILES) * WTILE)

// ---------------- persistent device scratch ---------------------------------
__device__ __nv_bfloat16 g_whi[WN];
__device__ __nv_bfloat16 g_wlo[WN];
__device__ float g_h0[2][NB * HD];
__device__ float g_c0[NB * HD];
__device__ float g_h1[2][NB * HD];
__device__ float g_c1[NB * HD];
__device__ float g_cls_sum;
__device__ float g_bbox_sum;
__device__ int   g_correct;
__device__ unsigned g_bar_count;
__device__ unsigned g_bar_phase;   // monotonic across replays

// ---------------- helpers ----------------------------------------------------
__device__ __forceinline__ uint32_t smem_u32(const void* p) {
    uint32_t a;
    asm("{ .reg .u64 t; cvta.to.shared.u64 t, %1; cvt.u32.u64 %0, t; }"
        : "=r"(a) : "l"(p));
    return a;
}
// pack: mem-low element x, mem-high element y (first cvt source -> high half)
__device__ __forceinline__ uint32_t packbf(float x, float y) {
    uint32_t r;
    asm("cvt.rn.bf16x2.f32 %0, %1, %2;" : "=r"(r) : "f"(y), "f"(x));
    return r;
}
__device__ __forceinline__ void mma_bf16(float* d, const uint32_t* a, const uint32_t* b) {
    asm volatile(
        "mma.sync.aligned.m16n8k16.row.col.f32.bf16.bf16.f32 "
        "{%0,%1,%2,%3}, {%4,%5,%6,%7}, {%8,%9}, {%0,%1,%2,%3};"
        : "+f"(d[0]), "+f"(d[1]), "+f"(d[2]), "+f"(d[3])
        : "r"(a[0]), "r"(a[1]), "r"(a[2]), "r"(a[3]), "r"(b[0]), "r"(b[1]));
}
#define CP16(dst, src) asm volatile("cp.async.cg.shared.global [%0], [%1], 16;" :: "r"(dst), "l"(src) : "memory")
#define CP_COMMIT()    asm volatile("cp.async.commit_group;" ::: "memory")
#define CP_WAIT0()     asm volatile("cp.async.wait_group 0;" ::: "memory")

// ---------------- software grid barrier --------------------------------------
__device__ __forceinline__ void grid_bar(unsigned& my_phase) {
    __syncthreads();
    if (threadIdx.x == 0) {
        __threadfence();
        unsigned old = atomicAdd(&g_bar_count, 1u);
        if (old == NBLK - 1) {
            g_bar_count = 0;
            __threadfence();
            atomicExch(&g_bar_phase, my_phase + 1u);
        } else {
            while (atomicAdd(&g_bar_phase, 0u) <= my_phase) __nanosleep(64);
        }
        __threadfence();
    }
    my_phase++;
    __syncthreads();
}

// ---------------- one LSTM layer-step (bf16x2 mma.sync + fused cell) ---------
__device__ __forceinline__ void lstm_step(
    const float* __restrict__ X, int xstr, int Kx,
    const float* __restrict__ Hprev,
    int wbase,
    const float* __restrict__ bias,
    float* __restrict__ cbuf, float* __restrict__ hout,
    uint32_t* smU, uint32_t su)
{
    const int tid  = threadIdx.x;
    const int lane = tid & 31;
    const int w    = tid >> 5;
    const int m0w  = (w >> 2) * 64;
    const int n0w  = (w & 3) * 32;
    const int tr   = lane >> 2;
    const int tc   = lane & 3;
    const int row0 = (blockIdx.x >> 4) * 128;
    const int j0   = (blockIdx.x & 15) * 32;
    const int nch0 = Kx / 32;
    const int ntot = nch0 + HD / 32;

    float d[4][4][4];
    #pragma unroll
    for (int mf = 0; mf < 4; ++mf)
        #pragma unroll
        for (int nf = 0; nf < 4; ++nf)
            #pragma unroll
            for (int q = 0; q < 4; ++q) d[mf][nf][q] = 0.f;

    float4 a4[4];

    #define LDG_A(kk_)  do {                                                   \
        const float* Ap; int astr_, k0_;                                       \
        if ((kk_) < nch0) { Ap = X;     astr_ = xstr; k0_ = (kk_) * 32; }      \
        else              { Ap = Hprev; astr_ = HD;   k0_ = ((kk_) - nch0) * 32; } \
        _Pragma("unroll")                                                      \
        for (int l = 0; l < 4; ++l) {                                          \
            int idx = tid + l * 256; int r = idx >> 3, fc = idx & 7;           \
            a4[l] = *reinterpret_cast<const float4*>(                          \
                &Ap[(size_t)(row0 + r) * astr_ + k0_ + fc * 4]);               \
        } } while (0)

    // convert + store A(kk+1) into stage s_ (hi/lo bf16)
    #define ST_A(s_)  do {                                                     \
        uint32_t* aHi = smU + (s_) * STAGE_U32;                                \
        uint32_t* aLo = aHi + TILE_U32;                                        \
        _Pragma("unroll")                                                      \
        for (int l = 0; l < 4; ++l) {                                          \
            int idx = tid + l * 256; int r = idx >> 3, fc = idx & 7;           \
            int so = r * RSTRIDE + fc * 2;                                     \
            float4 v = a4[l];                                                  \
            float hx = __bfloat162float(__float2bfloat16(v.x));                \
            float hy = __bfloat162float(__float2bfloat16(v.y));                \
            float hz = __bfloat162float(__float2bfloat16(v.z));                \
            float hw = __bfloat162float(__float2bfloat16(v.w));                \
            uint2 hv, lv;                                                      \
            hv.x = packbf(v.x, v.y);        hv.y = packbf(v.z, v.w);           \
            lv.x = packbf(v.x - hx, v.y - hy); lv.y = packbf(v.z - hz, v.w - hw); \
            *reinterpret_cast<uint2*>(&aHi[so]) = hv;                          \
            *reinterpret_cast<uint2*>(&aLo[so]) = lv;                          \
        } } while (0)

    #define CP_B(kk_, s_)  do {                                                \
        const __nv_bfloat16* srcHi = g_whi + (size_t)(wbase + (kk_)) * WTILE;  \
        const __nv_bfloat16* srcLo = g_wlo + (size_t)(wbase + (kk_)) * WTILE;  \
        uint32_t bHiA = su + ((s_) * STAGE_U32 + 2 * TILE_U32) * 4u;           \
        uint32_t bLoA = su + ((s_) * STAGE_U32 + 3 * TILE_U32) * 4u;           \
        _Pragma("unroll")                                                      \
        for (int l = 0; l < 2; ++l) {                                          \
            int idx = tid + l * 256; int r = idx >> 2, p = idx & 3;            \
            uint32_t doff = (uint32_t)(r * (RSTRIDE * 4) + p * 16);            \
            int soff = r * 32 + p * 8;                                         \
            CP16(bHiA + doff, srcHi + soff);                                   \
            CP16(bLoA + doff, srcLo + soff);                                   \
        } } while (0)

    // prologue: stage chunk 0 into buffer 0
    CP_B(0, 0); CP_COMMIT();
    LDG_A(0);
    ST_A(0);

    for (int kk = 0; kk < ntot; ++kk) {
        const int s = kk & 1;
        const bool pf = (kk + 1 < ntot);
        if (pf) LDG_A(kk + 1);           // long-latency global loads first
        CP_WAIT0();                       // B(kk) landed (only group in flight)
        __syncthreads();                  // publish stage s; retire readers of 1-s
        if (pf) { CP_B(kk + 1, 1 - s); CP_COMMIT(); }

        const uint32_t* aHiU = smU + s * STAGE_U32;
        const uint32_t* aLoU = aHiU + TILE_U32;
        const uint32_t* bHiU = aHiU + 2 * TILE_U32;
        const uint32_t* bLoU = aHiU + 3 * TILE_U32;

        #pragma unroll
        for (int kg = 0; kg < 2; ++kg) {
            const int kb = kg * 8;
            uint32_t ah[4][4], al[4][4];
            #pragma unroll
            for (int mf = 0; mf < 4; ++mf) {
                int rb = (m0w + mf * 16 + tr) * RSTRIDE + kb + tc;
                ah[mf][0] = aHiU[rb];
                ah[mf][1] = aHiU[rb + 8 * RSTRIDE];
                ah[mf][2] = aHiU[rb + 4];
                ah[mf][3] = aHiU[rb + 8 * RSTRIDE + 4];
                al[mf][0] = aLoU[rb];
                al[mf][1] = aLoU[rb + 8 * RSTRIDE];
                al[mf][2] = aLoU[rb + 4];
                al[mf][3] = aLoU[rb + 8 * RSTRIDE + 4];
            }
            #pragma unroll
            for (int nf = 0; nf < 4; ++nf) {
                int cb = (n0w + nf * 8 + tr) * RSTRIDE + kb + tc;
                uint32_t bh[2], bl[2];
                bh[0] = bHiU[cb];  bh[1] = bHiU[cb + 4];
                bl[0] = bLoU[cb];  bl[1] = bLoU[cb + 4];
                #pragma unroll
                for (int mf = 0; mf < 4; ++mf) {
                    mma_bf16(d[mf][nf], ah[mf], bh);
                    mma_bf16(d[mf][nf], ah[mf], bl);
                    mma_bf16(d[mf][nf], al[mf], bh);
                }
            }
        }

        if (pf) ST_A(1 - s);              // convert+store A(kk+1) into stage 1-s
    }

    #undef LDG_A
    #undef ST_A
    #undef CP_B

    // epilogue: gate exchange + fused cell pointwise
    #pragma unroll
    for (int mf = 0; mf < 4; ++mf) {
        #pragma unroll
        for (int nf = 0; nf < 4; ++nf) {
            float v0 = d[mf][nf][0], v1 = d[mf][nf][1];
            float v2 = d[mf][nf][2], v3 = d[mf][nf][3];
            float r0 = __shfl_xor_sync(0xffffffffu, v0, 1);
            float r1 = __shfl_xor_sync(0xffffffffu, v1, 1);
            float r2 = __shfl_xor_sync(0xffffffffu, v2, 1);
            float r3 = __shfl_xor_sync(0xffffffffu, v3, 1);
            if ((lane & 1) == 0) {
                int col = n0w + nf * 8 + tc * 2;
                int jj  = j0 + (col >> 2);
                int m   = row0 + m0w + mf * 16 + tr;
                float b0v = bias[jj], b1v = bias[HD + jj];
                float b2v = bias[2 * HD + jj], b3v = bias[3 * HD + jj];
                {
                    float gi = v0 + b0v, gf = v1 + b1v, gg = r0 + b2v, go = r1 + b3v;
                    float si = 1.f / (1.f + expf(-gi));
                    float sf = 1.f / (1.f + expf(-gf));
                    float so = 1.f / (1.f + expf(-go));
                    size_t ix = (size_t)m * HD + jj;
                    float cv = sf * cbuf[ix] + si * tanhf(gg);
                    cbuf[ix] = cv;
                    hout[ix] = so * tanhf(cv);
                }
                {
                    float gi = v2 + b0v, gf = v3 + b1v, gg = r2 + b2v, go = r3 + b3v;
                    float si = 1.f / (1.f + expf(-gi));
                    float sf = 1.f / (1.f + expf(-gf));
                    float so = 1.f / (1.f + expf(-go));
                    size_t ix = (size_t)(m + 8) * HD + jj;
                    float cv = sf * cbuf[ix] + si * tanhf(gg);
                    cbuf[ix] = cv;
                    hout[ix] = so * tanhf(cv);
                }
            }
        }
    }
}

// ---------------- whole network, one persistent kernel -----------------------
__global__ __launch_bounds__(NTHR, 1)
void rlstm_persistent(const float* __restrict__ data,
                      const int*   __restrict__ labels,
                      const float* __restrict__ props,
                      const float* __restrict__ Wih0, const float* __restrict__ Whh0,
                      const float* __restrict__ b0,
                      const float* __restrict__ Wih1, const float* __restrict__ Whh1,
                      const float* __restrict__ b1,
                      const float* __restrict__ Wcls, const float* __restrict__ bcls,
                      const float* __restrict__ Wbbox, const float* __restrict__ bbbox,
                      float* __restrict__ out)
{
    extern __shared__ uint32_t smU[];
    uint32_t su = smem_u32(smU);
    const int tid = threadIdx.x;
    unsigned ph = atomicAdd(&g_bar_phase, 0u);   // read BEFORE first arrive

    for (int i = blockIdx.x * NTHR + tid; i < NB * HD; i += NBLK * NTHR) {
        g_h0[0][i] = 0.f; g_h1[0][i] = 0.f;
        g_c0[i] = 0.f;    g_c1[i] = 0.f;
    }
    if (blockIdx.x == 0 && tid == 0) {
        g_cls_sum = 0.f; g_bbox_sum = 0.f; g_correct = 0;
    }
    // precompute hi/lo bf16 weights in packed (jt, chunk) tile order
    for (int i = blockIdx.x * NTHR + tid; i < WN; i += NBLK * NTHR) {
        int tile = i >> 12, e = i & 4095;
        int r = e >> 5, k = e & 31;
        int jt, kk;
        const float* B; int bstr, k0;
        if (tile < W0_TILES) {
            jt = tile / W0_NCH; kk = tile % W0_NCH;
            if (kk < 4) { B = Wih0; bstr = CH; k0 = kk * 32; }
            else        { B = Whh0; bstr = HD; k0 = (kk - 4) * 32; }
        } else {
            int t2 = tile - W0_TILES;
            jt = t2 / W1_NCH; kk = t2 % W1_NCH;
            if (kk < 16) { B = Wih1; bstr = HD; k0 = kk * 32; }
            else         { B = Whh1; bstr = HD; k0 = (kk - 16) * 32; }
        }
        int grow = (r & 3) * HD + jt * 32 + (r >> 2);
        float v = B[(size_t)grow * bstr + k0 + k];
        __nv_bfloat16 hb = __float2bfloat16(v);
        g_whi[i] = hb;
        g_wlo[i] = __float2bfloat16(v - __bfloat162float(hb));
    }
    grid_bar(ph);

    const int jt = blockIdx.x & 15;
    const int wbase0 = jt * W0_NCH;
    const int wbase1 = W0_TILES + jt * W1_NCH;

    for (int t = 0; t < SEQ; ++t) {
        int p = t & 1;
        lstm_step(data + (size_t)t * CH, SEQ * CH, CH,
                  g_h0[p], wbase0, b0, g_c0, g_h0[1 - p], smU, su);
        grid_bar(ph);
        lstm_step(g_h0[1 - p], HD, HD,
                  g_h1[p], wbase1, b1, g_c1, g_h1[1 - p], smU, su);
        grid_bar(ph);
    }

    // heads + loss on final hidden state g_h1[0]
    {
        float* hrow = (float*)smU;
        float* cls  = hrow + HD;
        for (int r = 0; r < 8; ++r) {
            int n = blockIdx.x * 8 + r;
            for (int j = tid; j < HD; j += NTHR)
                hrow[j] = g_h1[0][(size_t)n * HD + j];
            __syncthreads();
            if (tid < NCLS) {
                float s = bcls[tid];
                const float* wp = Wcls + (size_t)tid * HD;
                #pragma unroll 8
                for (int j = 0; j < HD; ++j) s += hrow[j] * wp[j];
                cls[tid] = s;
            } else if (tid < NCLS + 2) {
                int pp = tid - NCLS;
                float s = bbbox[pp];
                const float* wp = Wbbox + (size_t)pp * HD;
                #pragma unroll 8
                for (int j = 0; j < HD; ++j) s += hrow[j] * wp[j];
                float tg = props[n * 2 + pp] * (1.0f / (float)SEQ);
                float dd = fabsf(s - tg);
                float sl = (dd < 1.f) ? 0.5f * dd * dd : dd - 0.5f;
                atomicAdd(&g_bbox_sum, sl);
            }
            __syncthreads();
            if (tid == 0) {
                float mx = cls[0]; int am = 0;
                for (int k = 1; k < NCLS; ++k)
                    if (cls[k] > mx) { mx = cls[k]; am = k; }
                float se = 0.f;
                for (int k = 0; k < NCLS; ++k) se += expf(cls[k] - mx);
                float lse = mx + logf(se);
                int lbl = labels[n * 2];
                atomicAdd(&g_cls_sum, -(cls[lbl] - lse));
                if (am == lbl) atomicAdd(&g_correct, 1);
            }
            __syncthreads();
        }
    }
    grid_bar(ph);

    if (blockIdx.x == 0 && tid == 0) {
        out[0] = (g_cls_sum / (float)NB) / (1.0f + (float)g_correct);
        out[1] = (g_bbox_sum / (float)(NB * 2)) * 10.0f;
    }
}

// ---------------- launch: ONE graph node -------------------------------------
extern "C" void kernel_launch(void* const* d_in, const int* in_sizes, int n_in,
                              void* d_out, int out_size) {
    const float* data   = (const float*)d_in[0];
    const int*   labels = (const int*)  d_in[1];
    const float* props  = (const float*)d_in[2];
    const float* Wih0   = (const float*)d_in[3];
    const float* Whh0   = (const float*)d_in[4];
    const float* b0     = (const float*)d_in[5];
    const float* Wih1   = (const float*)d_in[6];
    const float* Whh1   = (const float*)d_in[7];
    const float* b1     = (const float*)d_in[8];
    const float* Wcls   = (const float*)d_in[9];
    const float* bcls   = (const float*)d_in[10];
    const float* Wbbox  = (const float*)d_in[11];
    const float* bbbox  = (const float*)d_in[12];
    float* out = (float*)d_out;

    cudaFuncSetAttribute(rlstm_persistent,
                         cudaFuncAttributeMaxDynamicSharedMemorySize, SMEM_SZ);
    rlstm_persistent<<<NBLK, NTHR, SMEM_SZ>>>(data, labels, props,
                                              Wih0, Whh0, b0, Wih1, Whh1, b1,
                                              Wcls, bcls, Wbbox, bbbox, out);
}

// round 9
// speedup vs baseline: 2.4162x; 1.0447x over previous
#include <cuda_runtime.h>
#include <cuda_bf16.h>
#include <math.h>
#include <stdint.h>

#define HD    512
#define GATES 2048
#define NB    1024
#define SEQ   256
#define CH    128
#define NCLS  40
#define NBLK  256          // 16 m-tiles x 16 j-tiles, 2 CTAs/SM
#define NTHR  256

// smem stage (u32): aHi|aLo (64 rows) + bHi|bLo (128 rows), RSTRIDE-padded
#define RSTRIDE 20
#define A_TILE_U32 (64 * RSTRIDE)      // 1280
#define B_TILE_U32 (128 * RSTRIDE)     // 2560
#define STAGE_U32 (2 * A_TILE_U32 + 2 * B_TILE_U32)   // 7680
#define SMEM_SZ (2 * STAGE_U32 * 4)    // 61440 bytes

// precomputed hi/lo bf16 weights, packed per (layer, jt, chunk) tile [128][32]
#define W0_NCH 20
#define W1_NCH 32
#define W0_TILES (16 * W0_NCH)
#define W1_TILES (16 * W1_NCH)
#define WTILE 4096
#define WN ((W0_TILES + W1_TILES) * WTILE)

// ---------------- persistent device scratch ---------------------------------
__device__ __nv_bfloat16 g_whi[WN];
__device__ __nv_bfloat16 g_wlo[WN];
__device__ float g_h0[2][NB * HD];
__device__ float g_c0[NB * HD];
__device__ float g_h1[2][NB * HD];
__device__ float g_c1[NB * HD];
__device__ float g_cls_sum;
__device__ float g_bbox_sum;
__device__ int   g_correct;
__device__ unsigned g_bar_count;
__device__ unsigned g_bar_phase;   // monotonic across replays

// ---------------- helpers ----------------------------------------------------
__device__ __forceinline__ uint32_t smem_u32(const void* p) {
    uint32_t a;
    asm("{ .reg .u64 t; cvta.to.shared.u64 t, %1; cvt.u32.u64 %0, t; }"
        : "=r"(a) : "l"(p));
    return a;
}
__device__ __forceinline__ uint32_t packbf(float x, float y) {
    uint32_t r;
    asm("cvt.rn.bf16x2.f32 %0, %1, %2;" : "=r"(r) : "f"(y), "f"(x));
    return r;
}
__device__ __forceinline__ void mma_bf16(float* d, const uint32_t* a, const uint32_t* b) {
    asm volatile(
        "mma.sync.aligned.m16n8k16.row.col.f32.bf16.bf16.f32 "
        "{%0,%1,%2,%3}, {%4,%5,%6,%7}, {%8,%9}, {%0,%1,%2,%3};"
        : "+f"(d[0]), "+f"(d[1]), "+f"(d[2]), "+f"(d[3])
        : "r"(a[0]), "r"(a[1]), "r"(a[2]), "r"(a[3]), "r"(b[0]), "r"(b[1]));
}
#define CP16(dst, src) asm volatile("cp.async.cg.shared.global [%0], [%1], 16;" :: "r"(dst), "l"(src) : "memory")
#define CP_COMMIT()    asm volatile("cp.async.commit_group;" ::: "memory")
#define CP_WAIT0()     asm volatile("cp.async.wait_group 0;" ::: "memory")

// ---------------- software grid barrier --------------------------------------
__device__ __forceinline__ void grid_bar(unsigned& my_phase) {
    __syncthreads();
    if (threadIdx.x == 0) {
        __threadfence();
        unsigned old = atomicAdd(&g_bar_count, 1u);
        if (old == NBLK - 1) {
            g_bar_count = 0;
            __threadfence();
            atomicExch(&g_bar_phase, my_phase + 1u);
        } else {
            while (atomicAdd(&g_bar_phase, 0u) <= my_phase) __nanosleep(64);
        }
        __threadfence();
    }
    my_phase++;
    __syncthreads();
}

// ---------------- one LSTM layer-step (bf16x2 mma.sync + fused cell) ---------
// block tile: 64 batch rows x 32 j (128 gate cols). 8 warps = 2m x 4n.
__device__ __forceinline__ void lstm_step(
    const float* __restrict__ X, int xstr, int Kx,
    const float* __restrict__ Hprev,
    int wbase,
    const float* __restrict__ bias,
    float* __restrict__ cbuf, float* __restrict__ hout,
    uint32_t* smU, uint32_t su)
{
    const int tid  = threadIdx.x;
    const int lane = tid & 31;
    const int w    = tid >> 5;
    const int m0w  = (w >> 2) * 32;        // warp m-offset (0 or 32)
    const int n0w  = (w & 3) * 32;         // warp n-offset
    const int tr   = lane >> 2;
    const int tc   = lane & 3;
    const int row0 = (blockIdx.x >> 4) * 64;
    const int j0   = (blockIdx.x & 15) * 32;
    const int nch0 = Kx / 32;
    const int ntot = nch0 + HD / 32;

    float d[2][4][4];
    #pragma unroll
    for (int mf = 0; mf < 2; ++mf)
        #pragma unroll
        for (int nf = 0; nf < 4; ++nf)
            #pragma unroll
            for (int q = 0; q < 4; ++q) d[mf][nf][q] = 0.f;

    float4 a4[2];

    #define LDG_A(kk_)  do {                                                   \
        const float* Ap; int astr_, k0_;                                       \
        if ((kk_) < nch0) { Ap = X;     astr_ = xstr; k0_ = (kk_) * 32; }      \
        else              { Ap = Hprev; astr_ = HD;   k0_ = ((kk_) - nch0) * 32; } \
        _Pragma("unroll")                                                      \
        for (int l = 0; l < 2; ++l) {                                          \
            int idx = tid + l * 256; int r = idx >> 3, fc = idx & 7;           \
            a4[l] = *reinterpret_cast<const float4*>(                          \
                &Ap[(size_t)(row0 + r) * astr_ + k0_ + fc * 4]);               \
        } } while (0)

    #define ST_A(s_)  do {                                                     \
        uint32_t* aHi = smU + (s_) * STAGE_U32;                                \
        uint32_t* aLo = aHi + A_TILE_U32;                                      \
        _Pragma("unroll")                                                      \
        for (int l = 0; l < 2; ++l) {                                          \
            int idx = tid + l * 256; int r = idx >> 3, fc = idx & 7;           \
            int so = r * RSTRIDE + fc * 2;                                     \
            float4 v = a4[l];                                                  \
            float hx = __bfloat162float(__float2bfloat16(v.x));                \
            float hy = __bfloat162float(__float2bfloat16(v.y));                \
            float hz = __bfloat162float(__float2bfloat16(v.z));                \
            float hw = __bfloat162float(__float2bfloat16(v.w));                \
            uint2 hv, lv;                                                      \
            hv.x = packbf(v.x, v.y);        hv.y = packbf(v.z, v.w);           \
            lv.x = packbf(v.x - hx, v.y - hy); lv.y = packbf(v.z - hz, v.w - hw); \
            *reinterpret_cast<uint2*>(&aHi[so]) = hv;                          \
            *reinterpret_cast<uint2*>(&aLo[so]) = lv;                          \
        } } while (0)

    #define CP_B(kk_, s_)  do {                                                \
        const __nv_bfloat16* srcHi = g_whi + (size_t)(wbase + (kk_)) * WTILE;  \
        const __nv_bfloat16* srcLo = g_wlo + (size_t)(wbase + (kk_)) * WTILE;  \
        uint32_t bHiA = su + ((s_) * STAGE_U32 + 2 * A_TILE_U32) * 4u;         \
        uint32_t bLoA = bHiA + B_TILE_U32 * 4u;                                \
        _Pragma("unroll")                                                      \
        for (int l = 0; l < 2; ++l) {                                          \
            int idx = tid + l * 256; int r = idx >> 2, p = idx & 3;            \
            uint32_t doff = (uint32_t)(r * (RSTRIDE * 4) + p * 16);            \
            int soff = r * 32 + p * 8;                                         \
            CP16(bHiA + doff, srcHi + soff);                                   \
            CP16(bLoA + doff, srcLo + soff);                                   \
        } } while (0)

    // prologue: stage chunk 0 into buffer 0
    CP_B(0, 0); CP_COMMIT();
    LDG_A(0);
    ST_A(0);

    for (int kk = 0; kk < ntot; ++kk) {
        const int s = kk & 1;
        const bool pf = (kk + 1 < ntot);
        if (pf) LDG_A(kk + 1);           // long-latency global loads first
        CP_WAIT0();                       // B(kk) landed
        __syncthreads();                  // publish stage s; retire readers of 1-s
        if (pf) { CP_B(kk + 1, 1 - s); CP_COMMIT(); }

        const uint32_t* aHiU = smU + s * STAGE_U32;
        const uint32_t* aLoU = aHiU + A_TILE_U32;
        const uint32_t* bHiU = aHiU + 2 * A_TILE_U32;
        const uint32_t* bLoU = bHiU + B_TILE_U32;

        #pragma unroll
        for (int kg = 0; kg < 2; ++kg) {
            const int kb = kg * 8;
            uint32_t ah[2][4], al[2][4];
            #pragma unroll
            for (int mf = 0; mf < 2; ++mf) {
                int rb = (m0w + mf * 16 + tr) * RSTRIDE + kb + tc;
                ah[mf][0] = aHiU[rb];
                ah[mf][1] = aHiU[rb + 8 * RSTRIDE];
                ah[mf][2] = aHiU[rb + 4];
                ah[mf][3] = aHiU[rb + 8 * RSTRIDE + 4];
                al[mf][0] = aLoU[rb];
                al[mf][1] = aLoU[rb + 8 * RSTRIDE];
                al[mf][2] = aLoU[rb + 4];
                al[mf][3] = aLoU[rb + 8 * RSTRIDE + 4];
            }
            #pragma unroll
            for (int nf = 0; nf < 4; ++nf) {
                int cb = (n0w + nf * 8 + tr) * RSTRIDE + kb + tc;
                uint32_t bh[2], bl[2];
                bh[0] = bHiU[cb];  bh[1] = bHiU[cb + 4];
                bl[0] = bLoU[cb];  bl[1] = bLoU[cb + 4];
                #pragma unroll
                for (int mf = 0; mf < 2; ++mf) {
                    mma_bf16(d[mf][nf], ah[mf], bh);
                    mma_bf16(d[mf][nf], ah[mf], bl);
                    mma_bf16(d[mf][nf], al[mf], bh);
                }
            }
        }

        if (pf) ST_A(1 - s);              // convert+store A(kk+1) into stage 1-s
    }

    #undef LDG_A
    #undef ST_A
    #undef CP_B

    // epilogue: gate exchange + fused cell pointwise
    #pragma unroll
    for (int mf = 0; mf < 2; ++mf) {
        #pragma unroll
        for (int nf = 0; nf < 4; ++nf) {
            float v0 = d[mf][nf][0], v1 = d[mf][nf][1];
            float v2 = d[mf][nf][2], v3 = d[mf][nf][3];
            float r0 = __shfl_xor_sync(0xffffffffu, v0, 1);
            float r1 = __shfl_xor_sync(0xffffffffu, v1, 1);
            float r2 = __shfl_xor_sync(0xffffffffu, v2, 1);
            float r3 = __shfl_xor_sync(0xffffffffu, v3, 1);
            if ((lane & 1) == 0) {
                int col = n0w + nf * 8 + tc * 2;
                int jj  = j0 + (col >> 2);
                int m   = row0 + m0w + mf * 16 + tr;
                float b0v = bias[jj], b1v = bias[HD + jj];
                float b2v = bias[2 * HD + jj], b3v = bias[3 * HD + jj];
                {
                    float gi = v0 + b0v, gf = v1 + b1v, gg = r0 + b2v, go = r1 + b3v;
                    float si = 1.f / (1.f + expf(-gi));
                    float sf = 1.f / (1.f + expf(-gf));
                    float so = 1.f / (1.f + expf(-go));
                    size_t ix = (size_t)m * HD + jj;
                    float cv = sf * cbuf[ix] + si * tanhf(gg);
                    cbuf[ix] = cv;
                    hout[ix] = so * tanhf(cv);
                }
                {
                    float gi = v2 + b0v, gf = v3 + b1v, gg = r2 + b2v, go = r3 + b3v;
                    float si = 1.f / (1.f + expf(-gi));
                    float sf = 1.f / (1.f + expf(-gf));
                    float so = 1.f / (1.f + expf(-go));
                    size_t ix = (size_t)(m + 8) * HD + jj;
                    float cv = sf * cbuf[ix] + si * tanhf(gg);
                    cbuf[ix] = cv;
                    hout[ix] = so * tanhf(cv);
                }
            }
        }
    }
}

// ---------------- whole network, one persistent kernel -----------------------
__global__ __launch_bounds__(NTHR, 2)
void rlstm_persistent(const float* __restrict__ data,
                      const int*   __restrict__ labels,
                      const float* __restrict__ props,
                      const float* __restrict__ Wih0, const float* __restrict__ Whh0,
                      const float* __restrict__ b0,
                      const float* __restrict__ Wih1, const float* __restrict__ Whh1,
                      const float* __restrict__ b1,
                      const float* __restrict__ Wcls, const float* __restrict__ bcls,
                      const float* __restrict__ Wbbox, const float* __restrict__ bbbox,
                      float* __restrict__ out)
{
    extern __shared__ uint32_t smU[];
    uint32_t su = smem_u32(smU);
    const int tid = threadIdx.x;
    unsigned ph = atomicAdd(&g_bar_phase, 0u);   // read BEFORE first arrive

    for (int i = blockIdx.x * NTHR + tid; i < NB * HD; i += NBLK * NTHR) {
        g_h0[0][i] = 0.f; g_h1[0][i] = 0.f;
        g_c0[i] = 0.f;    g_c1[i] = 0.f;
    }
    if (blockIdx.x == 0 && tid == 0) {
        g_cls_sum = 0.f; g_bbox_sum = 0.f; g_correct = 0;
    }
    // precompute hi/lo bf16 weights in packed (jt, chunk) tile order
    for (int i = blockIdx.x * NTHR + tid; i < WN; i += NBLK * NTHR) {
        int tile = i >> 12, e = i & 4095;
        int r = e >> 5, k = e & 31;
        int jt, kk;
        const float* B; int bstr, k0;
        if (tile < W0_TILES) {
            jt = tile / W0_NCH; kk = tile % W0_NCH;
            if (kk < 4) { B = Wih0; bstr = CH; k0 = kk * 32; }
            else        { B = Whh0; bstr = HD; k0 = (kk - 4) * 32; }
        } else {
            int t2 = tile - W0_TILES;
            jt = t2 / W1_NCH; kk = t2 % W1_NCH;
            if (kk < 16) { B = Wih1; bstr = HD; k0 = kk * 32; }
            else         { B = Whh1; bstr = HD; k0 = (kk - 16) * 32; }
        }
        int grow = (r & 3) * HD + jt * 32 + (r >> 2);
        float v = B[(size_t)grow * bstr + k0 + k];
        __nv_bfloat16 hb = __float2bfloat16(v);
        g_whi[i] = hb;
        g_wlo[i] = __float2bfloat16(v - __bfloat162float(hb));
    }
    grid_bar(ph);

    const int jt = blockIdx.x & 15;
    const int wbase0 = jt * W0_NCH;
    const int wbase1 = W0_TILES + jt * W1_NCH;

    for (int t = 0; t < SEQ; ++t) {
        int p = t & 1;
        lstm_step(data + (size_t)t * CH, SEQ * CH, CH,
                  g_h0[p], wbase0, b0, g_c0, g_h0[1 - p], smU, su);
        grid_bar(ph);
        lstm_step(g_h0[1 - p], HD, HD,
                  g_h1[p], wbase1, b1, g_c1, g_h1[1 - p], smU, su);
        grid_bar(ph);
    }

    // heads + loss on final hidden state g_h1[0]; 4 rows per block
    {
        float* hrow = (float*)smU;
        float* cls  = hrow + HD;
        for (int r = 0; r < 4; ++r) {
            int n = blockIdx.x * 4 + r;
            for (int j = tid; j < HD; j += NTHR)
                hrow[j] = g_h1[0][(size_t)n * HD + j];
            __syncthreads();
            if (tid < NCLS) {
                float s = bcls[tid];
                const float* wp = Wcls + (size_t)tid * HD;
                #pragma unroll 8
                for (int j = 0; j < HD; ++j) s += hrow[j] * wp[j];
                cls[tid] = s;
            } else if (tid < NCLS + 2) {
                int pp = tid - NCLS;
                float s = bbbox[pp];
                const float* wp = Wbbox + (size_t)pp * HD;
                #pragma unroll 8
                for (int j = 0; j < HD; ++j) s += hrow[j] * wp[j];
                float tg = props[n * 2 + pp] * (1.0f / (float)SEQ);
                float dd = fabsf(s - tg);
                float sl = (dd < 1.f) ? 0.5f * dd * dd : dd - 0.5f;
                atomicAdd(&g_bbox_sum, sl);
            }
            __syncthreads();
            if (tid == 0) {
                float mx = cls[0]; int am = 0;
                for (int k = 1; k < NCLS; ++k)
                    if (cls[k] > mx) { mx = cls[k]; am = k; }
                float se = 0.f;
                for (int k = 0; k < NCLS; ++k) se += expf(cls[k] - mx);
                float lse = mx + logf(se);
                int lbl = labels[n * 2];
                atomicAdd(&g_cls_sum, -(cls[lbl] - lse));
                if (am == lbl) atomicAdd(&g_correct, 1);
            }
            __syncthreads();
        }
    }
    grid_bar(ph);

    if (blockIdx.x == 0 && tid == 0) {
        out[0] = (g_cls_sum / (float)NB) / (1.0f + (float)g_correct);
        out[1] = (g_bbox_sum / (float)(NB * 2)) * 10.0f;
    }
}

// ---------------- launch: ONE graph node -------------------------------------
extern "C" void kernel_launch(void* const* d_in, const int* in_sizes, int n_in,
                              void* d_out, int out_size) {
    const float* data   = (const float*)d_in[0];
    const int*   labels = (const int*)  d_in[1];
    const float* props  = (const float*)d_in[2];
    const float* Wih0   = (const float*)d_in[3];
    const float* Whh0   = (const float*)d_in[4];
    const float* b0     = (const float*)d_in[5];
    const float* Wih1   = (const float*)d_in[6];
    const float* Whh1   = (const float*)d_in[7];
    const float* b1     = (const float*)d_in[8];
    const float* Wcls   = (const float*)d_in[9];
    const float* bcls   = (const float*)d_in[10];
    const float* Wbbox  = (const float*)d_in[11];
    const float* bbbox  = (const float*)d_in[12];
    float* out = (float*)d_out;

    cudaFuncSetAttribute(rlstm_persistent,
                         cudaFuncAttributeMaxDynamicSharedMemorySize, SMEM_SZ);
    rlstm_persistent<<<NBLK, NTHR, SMEM_SZ>>>(data, labels, props,
                                              Wih0, Whh0, b0, Wih1, Whh1, b1,
                                              Wcls, bcls, Wbbox, bbbox, out);
}

// round 10
// speedup vs baseline: 2.4846x; 1.0283x over previous
#include <cuda_runtime.h>
#include <cuda_bf16.h>
#include <math.h>
#include <stdint.h>

#define HD    512
#define GATES 2048
#define NB    1024
#define SEQ   256
#define CH    128
#define NCLS  40
#define NBLK  256          // 16 m-tiles x 16 j-tiles, 2 CTAs/SM
#define NTHR  256
#define NGRP  16           // blocks per barrier group (same mt, all jt)

// smem stage (u32): aHi|aLo (64 rows) + bHi|bLo (128 rows), RSTRIDE-padded
#define RSTRIDE 20
#define A_TILE_U32 (64 * RSTRIDE)      // 1280
#define B_TILE_U32 (128 * RSTRIDE)     // 2560
#define STAGE_U32 (2 * A_TILE_U32 + 2 * B_TILE_U32)   // 7680
#define SMEM_SZ (2 * STAGE_U32 * 4)    // 61440 bytes

// precomputed hi/lo bf16 weights, packed per (layer, jt, chunk) tile [128][32]
#define W0_NCH 20
#define W1_NCH 32
#define W0_TILES (16 * W0_NCH)
#define W1_TILES (16 * W1_NCH)
#define WTILE 4096
#define WN ((W0_TILES + W1_TILES) * WTILE)

// ---------------- persistent device scratch ---------------------------------
__device__ __nv_bfloat16 g_whi[WN];
__device__ __nv_bfloat16 g_wlo[WN];
__device__ float g_h0[2][NB * HD];
__device__ float g_c0[NB * HD];
__device__ float g_h1[2][NB * HD];
__device__ float g_c1[NB * HD];
__device__ float g_cls_sum;
__device__ float g_bbox_sum;
__device__ int   g_correct;
__device__ unsigned g_bar_count;
__device__ unsigned g_bar_phase;            // monotonic across replays
__device__ unsigned g_grp_count[16 * 32];   // padded: one 128B line per group
__device__ unsigned g_grp_phase[16 * 32];   // monotonic across replays

// ---------------- helpers ----------------------------------------------------
__device__ __forceinline__ uint32_t smem_u32(const void* p) {
    uint32_t a;
    asm("{ .reg .u64 t; cvta.to.shared.u64 t, %1; cvt.u32.u64 %0, t; }"
        : "=r"(a) : "l"(p));
    return a;
}
__device__ __forceinline__ uint32_t packbf(float x, float y) {
    uint32_t r;
    asm("cvt.rn.bf16x2.f32 %0, %1, %2;" : "=r"(r) : "f"(y), "f"(x));
    return r;
}
__device__ __forceinline__ void mma_bf16(float* d, const uint32_t* a,
                                         uint32_t b0, uint32_t b1) {
    asm volatile(
        "mma.sync.aligned.m16n8k16.row.col.f32.bf16.bf16.f32 "
        "{%0,%1,%2,%3}, {%4,%5,%6,%7}, {%8,%9}, {%0,%1,%2,%3};"
        : "+f"(d[0]), "+f"(d[1]), "+f"(d[2]), "+f"(d[3])
        : "r"(a[0]), "r"(a[1]), "r"(a[2]), "r"(a[3]), "r"(b0), "r"(b1));
}
__device__ __forceinline__ void ldsm_x4(uint32_t* r, uint32_t addr) {
    asm volatile("ldmatrix.sync.aligned.m8n8.x4.shared.b16 {%0,%1,%2,%3}, [%4];"
        : "=r"(r[0]), "=r"(r[1]), "=r"(r[2]), "=r"(r[3]) : "r"(addr));
}
#define CP16(dst, src) asm volatile("cp.async.cg.shared.global [%0], [%1], 16;" :: "r"(dst), "l"(src) : "memory")
#define CP_COMMIT()    asm volatile("cp.async.commit_group;" ::: "memory")
#define CP_WAIT0()     asm volatile("cp.async.wait_group 0;" ::: "memory")

// ---------------- barriers ----------------------------------------------------
__device__ __forceinline__ void grid_bar(unsigned& my_phase) {
    __syncthreads();
    if (threadIdx.x == 0) {
        __threadfence();
        unsigned old = atomicAdd(&g_bar_count, 1u);
        if (old == NBLK - 1) {
            g_bar_count = 0;
            __threadfence();
            atomicExch(&g_bar_phase, my_phase + 1u);
        } else {
            while (atomicAdd(&g_bar_phase, 0u) <= my_phase) __nanosleep(64);
        }
        __threadfence();
    }
    my_phase++;
    __syncthreads();
}

// 16-block barrier over the group sharing one m-tile (all inter-step deps local)
__device__ __forceinline__ void group_bar(int grp, unsigned& my_phase) {
    __syncthreads();
    if (threadIdx.x == 0) {
        __threadfence();
        unsigned old = atomicAdd(&g_grp_count[grp * 32], 1u);
        if (old == NGRP - 1) {
            g_grp_count[grp * 32] = 0;
            __threadfence();
            atomicExch(&g_grp_phase[grp * 32], my_phase + 1u);
        } else {
            while (atomicAdd(&g_grp_phase[grp * 32], 0u) <= my_phase) __nanosleep(32);
        }
        __threadfence();
    }
    my_phase++;
    __syncthreads();
}

// ---------------- one LSTM layer-step (ldmatrix + bf16 mma + fused cell) -----
// block tile: 64 batch rows x 32 j (128 gate cols). 8 warps = 2m x 4n.
__device__ __forceinline__ void lstm_step(
    const float* __restrict__ X, int xstr, int Kx,
    const float* __restrict__ Hprev,
    int wbase,
    const float* __restrict__ bias,
    float* __restrict__ cbuf, float* __restrict__ hout,
    uint32_t* smU, uint32_t su)
{
    const int tid  = threadIdx.x;
    const int lane = tid & 31;
    const int w    = tid >> 5;
    const int m0w  = (w >> 2) * 32;
    const int n0w  = (w & 3) * 32;
    const int tr   = lane >> 2;
    const int tc   = lane & 3;
    const int row0 = (blockIdx.x >> 4) * 64;
    const int j0   = (blockIdx.x & 15) * 32;
    const int nch0 = Kx / 32;
    const int ntot = nch0 + HD / 32;

    // ldmatrix lane address components (u32 units within a tile)
    const int lrow16 = lane & 15;          // row within 16-row tile group
    const int lkoff  = (lane >> 4) << 2;   // +4 u32 words (=16B) for k8 tiles

    float d[2][4][4];
    #pragma unroll
    for (int mf = 0; mf < 2; ++mf)
        #pragma unroll
        for (int nf = 0; nf < 4; ++nf)
            #pragma unroll
            for (int q = 0; q < 4; ++q) d[mf][nf][q] = 0.f;

    float4 a4[2];

    #define LDG_A(kk_)  do {                                                   \
        const float* Ap; int astr_, k0_;                                       \
        if ((kk_) < nch0) { Ap = X;     astr_ = xstr; k0_ = (kk_) * 32; }      \
        else              { Ap = Hprev; astr_ = HD;   k0_ = ((kk_) - nch0) * 32; } \
        _Pragma("unroll")                                                      \
        for (int l = 0; l < 2; ++l) {                                          \
            int idx = tid + l * 256; int r = idx >> 3, fc = idx & 7;           \
            a4[l] = *reinterpret_cast<const float4*>(                          \
                &Ap[(size_t)(row0 + r) * astr_ + k0_ + fc * 4]);               \
        } } while (0)

    #define ST_A(s_)  do {                                                     \
        uint32_t* aHi = smU + (s_) * STAGE_U32;                                \
        uint32_t* aLo = aHi + A_TILE_U32;                                      \
        _Pragma("unroll")                                                      \
        for (int l = 0; l < 2; ++l) {                                          \
            int idx = tid + l * 256; int r = idx >> 3, fc = idx & 7;           \
            int so = r * RSTRIDE + fc * 2;                                     \
            float4 v = a4[l];                                                  \
            float hx = __bfloat162float(__float2bfloat16(v.x));                \
            float hy = __bfloat162float(__float2bfloat16(v.y));                \
            float hz = __bfloat162float(__float2bfloat16(v.z));                \
            float hw = __bfloat162float(__float2bfloat16(v.w));                \
            uint2 hv, lv;                                                      \
            hv.x = packbf(v.x, v.y);        hv.y = packbf(v.z, v.w);           \
            lv.x = packbf(v.x - hx, v.y - hy); lv.y = packbf(v.z - hz, v.w - hw); \
            *reinterpret_cast<uint2*>(&aHi[so]) = hv;                          \
            *reinterpret_cast<uint2*>(&aLo[so]) = lv;                          \
        } } while (0)

    #define CP_B(kk_, s_)  do {                                                \
        const __nv_bfloat16* srcHi = g_whi + (size_t)(wbase + (kk_)) * WTILE;  \
        const __nv_bfloat16* srcLo = g_wlo + (size_t)(wbase + (kk_)) * WTILE;  \
        uint32_t bHiA = su + ((s_) * STAGE_U32 + 2 * A_TILE_U32) * 4u;         \
        uint32_t bLoA = bHiA + B_TILE_U32 * 4u;                                \
        _Pragma("unroll")                                                      \
        for (int l = 0; l < 2; ++l) {                                          \
            int idx = tid + l * 256; int r = idx >> 2, p = idx & 3;            \
            uint32_t doff = (uint32_t)(r * (RSTRIDE * 4) + p * 16);            \
            int soff = r * 32 + p * 8;                                         \
            CP16(bHiA + doff, srcHi + soff);                                   \
            CP16(bLoA + doff, srcLo + soff);                                   \
        } } while (0)

    // prologue: stage chunk 0 into buffer 0
    CP_B(0, 0); CP_COMMIT();
    LDG_A(0);
    ST_A(0);

    for (int kk = 0; kk < ntot; ++kk) {
        const int s = kk & 1;
        const bool pf = (kk + 1 < ntot);
        if (pf) LDG_A(kk + 1);           // long-latency global loads first
        CP_WAIT0();                       // B(kk) landed
        __syncthreads();                  // publish stage s; retire readers of 1-s
        if (pf) { CP_B(kk + 1, 1 - s); CP_COMMIT(); }

        const uint32_t stage = su + s * STAGE_U32 * 4u;
        const uint32_t aHiB  = stage;
        const uint32_t bHiB  = stage + (2 * A_TILE_U32) * 4u;

        #pragma unroll
        for (int kg = 0; kg < 2; ++kg) {
            const int kb = kg * 8;
            uint32_t ah[2][4], al[2][4];     // [mf][reg]
            uint32_t bh[2][4], bl[2][4];     // [nf-pair][reg]
            #pragma unroll
            for (int mf = 0; mf < 2; ++mf) {
                uint32_t aaddr = aHiB +
                    (uint32_t)(((m0w + mf * 16 + lrow16) * RSTRIDE + kb + lkoff) * 4);
                ldsm_x4(ah[mf], aaddr);
                ldsm_x4(al[mf], aaddr + A_TILE_U32 * 4u);
            }
            #pragma unroll
            for (int np = 0; np < 2; ++np) {
                uint32_t baddr = bHiB +
                    (uint32_t)(((n0w + np * 16 + lrow16) * RSTRIDE + kb + lkoff) * 4);
                ldsm_x4(bh[np], baddr);
                ldsm_x4(bl[np], baddr + B_TILE_U32 * 4u);
            }
            #pragma unroll
            for (int nf = 0; nf < 4; ++nf) {
                const int np = nf >> 1, sel = nf & 1;
                uint32_t b0h = bh[np][sel], b1h = bh[np][sel + 2];
                uint32_t b0l = bl[np][sel], b1l = bl[np][sel + 2];
                #pragma unroll
                for (int mf = 0; mf < 2; ++mf) {
                    mma_bf16(d[mf][nf], ah[mf], b0h, b1h);
                    mma_bf16(d[mf][nf], ah[mf], b0l, b1l);
                    mma_bf16(d[mf][nf], al[mf], b0h, b1h);
                }
            }
        }

        if (pf) ST_A(1 - s);              // convert+store A(kk+1) into stage 1-s
    }

    #undef LDG_A
    #undef ST_A
    #undef CP_B

    // epilogue: gate exchange + fused cell pointwise
    #pragma unroll
    for (int mf = 0; mf < 2; ++mf) {
        #pragma unroll
        for (int nf = 0; nf < 4; ++nf) {
            float v0 = d[mf][nf][0], v1 = d[mf][nf][1];
            float v2 = d[mf][nf][2], v3 = d[mf][nf][3];
            float r0 = __shfl_xor_sync(0xffffffffu, v0, 1);
            float r1 = __shfl_xor_sync(0xffffffffu, v1, 1);
            float r2 = __shfl_xor_sync(0xffffffffu, v2, 1);
            float r3 = __shfl_xor_sync(0xffffffffu, v3, 1);
            if ((lane & 1) == 0) {
                int col = n0w + nf * 8 + tc * 2;
                int jj  = j0 + (col >> 2);
                int m   = row0 + m0w + mf * 16 + tr;
                float b0v = bias[jj], b1v = bias[HD + jj];
                float b2v = bias[2 * HD + jj], b3v = bias[3 * HD + jj];
                {
                    float gi = v0 + b0v, gf = v1 + b1v, gg = r0 + b2v, go = r1 + b3v;
                    float si = 1.f / (1.f + expf(-gi));
                    float sf = 1.f / (1.f + expf(-gf));
                    float so = 1.f / (1.f + expf(-go));
                    size_t ix = (size_t)m * HD + jj;
                    float cv = sf * cbuf[ix] + si * tanhf(gg);
                    cbuf[ix] = cv;
                    hout[ix] = so * tanhf(cv);
                }
                {
                    float gi = v2 + b0v, gf = v3 + b1v, gg = r2 + b2v, go = r3 + b3v;
                    float si = 1.f / (1.f + expf(-gi));
                    float sf = 1.f / (1.f + expf(-gf));
                    float so = 1.f / (1.f + expf(-go));
                    size_t ix = (size_t)(m + 8) * HD + jj;
                    float cv = sf * cbuf[ix] + si * tanhf(gg);
                    cbuf[ix] = cv;
                    hout[ix] = so * tanhf(cv);
                }
            }
        }
    }
}

// ---------------- whole network, one persistent kernel -----------------------
__global__ __launch_bounds__(NTHR, 2)
void rlstm_persistent(const float* __restrict__ data,
                      const int*   __restrict__ labels,
                      const float* __restrict__ props,
                      const float* __restrict__ Wih0, const float* __restrict__ Whh0,
                      const float* __restrict__ b0,
                      const float* __restrict__ Wih1, const float* __restrict__ Whh1,
                      const float* __restrict__ b1,
                      const float* __restrict__ Wcls, const float* __restrict__ bcls,
                      const float* __restrict__ Wbbox, const float* __restrict__ bbbox,
                      float* __restrict__ out)
{
    extern __shared__ uint32_t smU[];
    uint32_t su = smem_u32(smU);
    const int tid = threadIdx.x;
    const int grp = blockIdx.x >> 4;             // m-tile group
    unsigned ph  = atomicAdd(&g_bar_phase, 0u);           // read BEFORE first arrive
    unsigned gph = atomicAdd(&g_grp_phase[grp * 32], 0u); // read BEFORE first arrive

    for (int i = blockIdx.x * NTHR + tid; i < NB * HD; i += NBLK * NTHR) {
        g_h0[0][i] = 0.f; g_h1[0][i] = 0.f;
        g_c0[i] = 0.f;    g_c1[i] = 0.f;
    }
    if (blockIdx.x == 0 && tid == 0) {
        g_cls_sum = 0.f; g_bbox_sum = 0.f; g_correct = 0;
    }
    // precompute hi/lo bf16 weights in packed (jt, chunk) tile order
    for (int i = blockIdx.x * NTHR + tid; i < WN; i += NBLK * NTHR) {
        int tile = i >> 12, e = i & 4095;
        int r = e >> 5, k = e & 31;
        int jt, kk;
        const float* B; int bstr, k0;
        if (tile < W0_TILES) {
            jt = tile / W0_NCH; kk = tile % W0_NCH;
            if (kk < 4) { B = Wih0; bstr = CH; k0 = kk * 32; }
            else        { B = Whh0; bstr = HD; k0 = (kk - 4) * 32; }
        } else {
            int t2 = tile - W0_TILES;
            jt = t2 / W1_NCH; kk = t2 % W1_NCH;
            if (kk < 16) { B = Wih1; bstr = HD; k0 = kk * 32; }
            else         { B = Whh1; bstr = HD; k0 = (kk - 16) * 32; }
        }
        int grow = (r & 3) * HD + jt * 32 + (r >> 2);
        float v = B[(size_t)grow * bstr + k0 + k];
        __nv_bfloat16 hb = __float2bfloat16(v);
        g_whi[i] = hb;
        g_wlo[i] = __float2bfloat16(v - __bfloat162float(hb));
    }
    grid_bar(ph);

    const int jt = blockIdx.x & 15;
    const int wbase0 = jt * W0_NCH;
    const int wbase1 = W0_TILES + jt * W1_NCH;

    for (int t = 0; t < SEQ; ++t) {
        int p = t & 1;
        lstm_step(data + (size_t)t * CH, SEQ * CH, CH,
                  g_h0[p], wbase0, b0, g_c0, g_h0[1 - p], smU, su);
        group_bar(grp, gph);
        lstm_step(g_h0[1 - p], HD, HD,
                  g_h1[p], wbase1, b1, g_c1, g_h1[1 - p], smU, su);
        group_bar(grp, gph);
    }
    grid_bar(ph);   // all groups done before cross-group h1 reads

    // heads + loss on final hidden state g_h1[0]; 4 rows per block
    {
        float* hrow = (float*)smU;
        float* cls  = hrow + HD;
        for (int r = 0; r < 4; ++r) {
            int n = blockIdx.x * 4 + r;
            for (int j = tid; j < HD; j += NTHR)
                hrow[j] = g_h1[0][(size_t)n * HD + j];
            __syncthreads();
            if (tid < NCLS) {
                float s = bcls[tid];
                const float* wp = Wcls + (size_t)tid * HD;
                #pragma unroll 8
                for (int j = 0; j < HD; ++j) s += hrow[j] * wp[j];
                cls[tid] = s;
            } else if (tid < NCLS + 2) {
                int pp = tid - NCLS;
                float s = bbbox[pp];
                const float* wp = Wbbox + (size_t)pp * HD;
                #pragma unroll 8
                for (int j = 0; j < HD; ++j) s += hrow[j] * wp[j];
                float tg = props[n * 2 + pp] * (1.0f / (float)SEQ);
                float dd = fabsf(s - tg);
                float sl = (dd < 1.f) ? 0.5f * dd * dd : dd - 0.5f;
                atomicAdd(&g_bbox_sum, sl);
            }
            __syncthreads();
            if (tid == 0) {
                float mx = cls[0]; int am = 0;
                for (int k = 1; k < NCLS; ++k)
                    if (cls[k] > mx) { mx = cls[k]; am = k; }
                float se = 0.f;
                for (int k = 0; k < NCLS; ++k) se += expf(cls[k] - mx);
                float lse = mx + logf(se);
                int lbl = labels[n * 2];
                atomicAdd(&g_cls_sum, -(cls[lbl] - lse));
                if (am == lbl) atomicAdd(&g_correct, 1);
            }
            __syncthreads();
        }
    }
    grid_bar(ph);

    if (blockIdx.x == 0 && tid == 0) {
        out[0] = (g_cls_sum / (float)NB) / (1.0f + (float)g_correct);
        out[1] = (g_bbox_sum / (float)(NB * 2)) * 10.0f;
    }
}

// ---------------- launch: ONE graph node -------------------------------------
extern "C" void kernel_launch(void* const* d_in, const int* in_sizes, int n_in,
                              void* d_out, int out_size) {
    const float* data   = (const float*)d_in[0];
    const int*   labels = (const int*)  d_in[1];
    const float* props  = (const float*)d_in[2];
    const float* Wih0   = (const float*)d_in[3];
    const float* Whh0   = (const float*)d_in[4];
    const float* b0     = (const float*)d_in[5];
    const float* Wih1   = (const float*)d_in[6];
    const float* Whh1   = (const float*)d_in[7];
    const float* b1     = (const float*)d_in[8];
    const float* Wcls   = (const float*)d_in[9];
    const float* bcls   = (const float*)d_in[10];
    const float* Wbbox  = (const float*)d_in[11];
    const float* bbbox  = (const float*)d_in[12];
    float* out = (float*)d_out;

    cudaFuncSetAttribute(rlstm_persistent,
                         cudaFuncAttributeMaxDynamicSharedMemorySize, SMEM_SZ);
    rlstm_persistent<<<NBLK, NTHR, SMEM_SZ>>>(data, labels, props,
                                              Wih0, Whh0, b0, Wih1, Whh1, b1,
                                              Wcls, bcls, Wbbox, bbbox, out);
}